// round 4
// baseline (speedup 1.0000x reference)
#include <cuda_runtime.h>
#include <cuda_bf16.h>
#include <cstdint>
#include <cmath>

// ---------------- problem constants ----------------
#define LL 2
#define HH 24
#define KVH 8
#define GG 3
#define DD 128
#define ROT 96
#define HALF 48
#define HID 3072
#define FF 8192
#define VV 32000
#define SS 1024
#define QP (HH*DD)          // 3072
#define KP (KVH*DD)         // 1024
#define QKV_O (QP + 2*KP)   // 5120
#define EPS 1e-6f
// SCALE = D^(-0.25)
__device__ __constant__ float SCALE_C = 0.29730177875068026f;

// ---------------- scratch (single device symbol, no allocations) -----------
#define OFF_H      0ull
#define OFF_HN     (OFF_H   + (size_t)SS*HID)
#define OFF_QKV    (OFF_HN  + (size_t)SS*HID)
#define OFF_Q      (OFF_QKV + (size_t)SS*QKV_O)
#define OFF_SC     (OFF_Q   + (size_t)HH*SS*DD)
#define OFF_AO     (OFF_SC  + (size_t)HH*SS*SS)
#define OFF_GU     (OFF_AO  + (size_t)SS*HID)
#define OFF_ACT    (OFF_GU  + (size_t)SS*2*FF)
#define OFF_HL     (OFF_ACT + (size_t)SS*FF)
#define OFF_LG     (OFF_HL  + (size_t)HID)
#define OFF_FLAG   (OFF_LG  + (size_t)VV)
#define SCRATCH_TOTAL (OFF_FLAG + 16)

__device__ float g_scratch[SCRATCH_TOTAL];

// output layout (4-byte elements)
#define OUT_KEYS   0ull
#define OUT_VALS   ((size_t)LL*KVH*DD*SS)
#define OUT_KVLEN  (2ull*LL*KVH*DD*SS)
#define OUT_TOKEN  (OUT_KVLEN + 1)

// ---------------- dtype probe for embed_q ----------------
// mode: 0 = uint8, 1 = int32, 2 = float32, 3 = bfloat16
__global__ void detect_dtype_kernel(const unsigned int* __restrict__ w,
                                    int* __restrict__ mode)
{
    bool all_small = true, all_f32 = true, all_bf16 = true;
    for (int i = 0; i < 64; i++) {
        unsigned int x = w[i];
        if (x > 255u) all_small = false;
        float f = __uint_as_float(x);
        if (!(f >= 0.f && f <= 255.f && f == rintf(f))) all_f32 = false;
        float f0 = __uint_as_float(x << 16);          // low half as bf16
        float f1 = __uint_as_float(x & 0xFFFF0000u);  // high half as bf16
        if (!(f0 >= 0.f && f0 <= 255.f && f0 == rintf(f0) &&
              f1 >= 0.f && f1 <= 255.f && f1 == rintf(f1))) all_bf16 = false;
    }
    *mode = all_small ? 1 : (all_f32 ? 2 : (all_bf16 ? 3 : 0));
}

// ---------------- embed: h[s,:] = q[id]*scale[id] + zero[id] ----------------
__global__ void embed_kernel(const int* __restrict__ ids,
                             const void* __restrict__ eq,
                             const float* __restrict__ escale,
                             const float* __restrict__ ezero,
                             const int* __restrict__ modep,
                             float* __restrict__ h)
{
    int s = blockIdx.x;
    int id = ids[s];
    float sc = escale[id], z = ezero[id];
    float* out = h + (size_t)s * HID;
    int mode = *modep;
    if (mode == 1) {
        const int* row = (const int*)eq + (size_t)id * HID;
        for (int j = threadIdx.x; j < HID; j += blockDim.x)
            out[j] = (float)row[j] * sc + z;
    } else if (mode == 2) {
        const float* row = (const float*)eq + (size_t)id * HID;
        for (int j = threadIdx.x; j < HID; j += blockDim.x)
            out[j] = row[j] * sc + z;
    } else if (mode == 3) {
        const unsigned short* row = (const unsigned short*)eq + (size_t)id * HID;
        for (int j = threadIdx.x; j < HID; j += blockDim.x)
            out[j] = __uint_as_float(((unsigned int)row[j]) << 16) * sc + z;
    } else {
        const unsigned char* row = (const unsigned char*)eq + (size_t)id * HID;
        for (int j = threadIdx.x; j < HID; j += blockDim.x)
            out[j] = (float)row[j] * sc + z;
    }
}

// ---------------- RMSNorm ----------------
__global__ void rmsnorm_kernel(const float* __restrict__ in,
                               const float* __restrict__ w,
                               float* __restrict__ out, int n)
{
    __shared__ float red[256];
    int row = blockIdx.x;
    const float* x = in + (size_t)row * n;
    float* y = out + (size_t)row * n;
    float s = 0.f;
    for (int i = threadIdx.x; i < n; i += 256) { float v = x[i]; s += v * v; }
    red[threadIdx.x] = s; __syncthreads();
    for (int st = 128; st > 0; st >>= 1) {
        if (threadIdx.x < st) red[threadIdx.x] += red[threadIdx.x + st];
        __syncthreads();
    }
    float inv = rsqrtf(red[0] / (float)n + EPS);
    for (int i = threadIdx.x; i < n; i += 256)
        y[i] = w[i] * x[i] * inv;
}

// ---------------- generic batched 128x128x8 SGEMM ----------------
// C[M,N] (z-batched) = A[M,K] * B  where B is (N,K) row-major if TRANSB
// else (K,N) row-major. B batch index = z / gdivB (GQA sharing).
template<bool TRANSB, bool ACC>
__global__ __launch_bounds__(256) void sgemm_kernel(
    const float* __restrict__ A, int lda, long sA,
    const float* __restrict__ B, int ldb, long sB, int gdivB,
    float* __restrict__ C, int ldc, long sC,
    int K)
{
    __shared__ float As[8][128];
    __shared__ float Bs[8][128];
    int bz = blockIdx.z;
    A += (long)bz * sA;
    B += (long)(bz / gdivB) * sB;
    C += (long)bz * sC;
    int m0 = blockIdx.y * 128, n0 = blockIdx.x * 128;
    int tid = threadIdx.x;
    int tx = tid & 15, ty = tid >> 4;
    int arow = tid >> 1, acol = (tid & 1) * 4;

    float acc[8][8];
#pragma unroll
    for (int i = 0; i < 8; i++)
#pragma unroll
        for (int j = 0; j < 8; j++) acc[i][j] = 0.f;

    for (int k0 = 0; k0 < K; k0 += 8) {
        float4 av = *(const float4*)(A + (long)(m0 + arow) * lda + k0 + acol);
        As[acol + 0][arow] = av.x; As[acol + 1][arow] = av.y;
        As[acol + 2][arow] = av.z; As[acol + 3][arow] = av.w;
        if (TRANSB) {
            float4 bv = *(const float4*)(B + (long)(n0 + arow) * ldb + k0 + acol);
            Bs[acol + 0][arow] = bv.x; Bs[acol + 1][arow] = bv.y;
            Bs[acol + 2][arow] = bv.z; Bs[acol + 3][arow] = bv.w;
        } else {
            int brow = tid >> 5, bcol = (tid & 31) * 4;
            float4 bv = *(const float4*)(B + (long)(k0 + brow) * ldb + n0 + bcol);
            *(float4*)&Bs[brow][bcol] = bv;
        }
        __syncthreads();
#pragma unroll
        for (int kk = 0; kk < 8; kk++) {
            float4 a0 = *(const float4*)&As[kk][ty * 8];
            float4 a1 = *(const float4*)&As[kk][ty * 8 + 4];
            float4 b0 = *(const float4*)&Bs[kk][tx * 8];
            float4 b1 = *(const float4*)&Bs[kk][tx * 8 + 4];
            float a[8] = {a0.x, a0.y, a0.z, a0.w, a1.x, a1.y, a1.z, a1.w};
            float b[8] = {b0.x, b0.y, b0.z, b0.w, b1.x, b1.y, b1.z, b1.w};
#pragma unroll
            for (int i = 0; i < 8; i++)
#pragma unroll
                for (int j = 0; j < 8; j++)
                    acc[i][j] = fmaf(a[i], b[j], acc[i][j]);
        }
        __syncthreads();
    }
#pragma unroll
    for (int i = 0; i < 8; i++) {
        int m = m0 + ty * 8 + i;
        float* cr = C + (long)m * ldc + n0 + tx * 8;
#pragma unroll
        for (int j = 0; j < 8; j++) {
            if (ACC) cr[j] += acc[i][j];
            else     cr[j] = acc[i][j];
        }
    }
}

// ---------------- split qkv + rope + scale; write K/V caches to d_out -------
__global__ void rope_split_kernel(const float* __restrict__ qkv,
                                  const float* __restrict__ cosE,
                                  const float* __restrict__ sinE,
                                  float* __restrict__ qout,     // [H][S][D]
                                  float* __restrict__ keys,     // [KV][D][S]
                                  float* __restrict__ vals)     // [KV][S][D]
{
    long idx = (long)blockIdx.x * blockDim.x + threadIdx.x;
    if (idx >= (long)SS * QKV_O) return;
    int s = (int)(idx / QKV_O);
    int c = (int)(idx % QKV_O);
    float v = qkv[idx];
    float scale = SCALE_C;
    if (c < QP) {
        int hh = c / DD, d = c % DD;
        float val = v * scale;
        if (d < ROT) {
            int pd = (d < HALF) ? d + HALF : d - HALF;
            float partner = qkv[(long)s * QKV_O + hh * DD + pd] * scale;
            float r = (d < HALF) ? -partner : partner;
            val = val * cosE[s * ROT + d] + r * sinE[s * ROT + d];
        }
        qout[((size_t)hh * SS + s) * DD + d] = val;
    } else if (c < QP + KP) {
        int kc = c - QP;
        int kv = kc / DD, d = kc % DD;
        float val = v * scale;
        if (d < ROT) {
            int pd = (d < HALF) ? d + HALF : d - HALF;
            float partner = qkv[(long)s * QKV_O + QP + kv * DD + pd] * scale;
            float r = (d < HALF) ? -partner : partner;
            val = val * cosE[s * ROT + d] + r * sinE[s * ROT + d];
        }
        keys[((size_t)kv * DD + d) * SS + s] = val;
    } else {
        int vc = c - QP - KP;
        int kv = vc / DD, d = vc % DD;
        vals[((size_t)kv * SS + s) * DD + d] = v;
    }
}

// ---------------- softmax with causal additive mask -128*mask_flag ----------
__global__ void softmax_kernel(float* __restrict__ sc, const int* __restrict__ maskf)
{
    __shared__ float red[256];
    int s = blockIdx.x, h = blockIdx.y;
    float* row = sc + ((size_t)h * SS + s) * SS;
    int mflag = maskf ? *maskf : 1;
    float mf = -128.f * (float)mflag;
    int tid = threadIdx.x;
    float vals[4];
    float lmax = -3.4e38f;
#pragma unroll
    for (int i = 0; i < 4; i++) {
        int t = tid + i * 256;
        float x = row[t] + ((t <= s) ? 0.f : mf);
        vals[i] = x;
        lmax = fmaxf(lmax, x);
    }
    red[tid] = lmax; __syncthreads();
    for (int st = 128; st > 0; st >>= 1) {
        if (tid < st) red[tid] = fmaxf(red[tid], red[tid + st]);
        __syncthreads();
    }
    float mx = red[0]; __syncthreads();
    float lsum = 0.f;
#pragma unroll
    for (int i = 0; i < 4; i++) { vals[i] = expf(vals[i] - mx); lsum += vals[i]; }
    red[tid] = lsum; __syncthreads();
    for (int st = 128; st > 0; st >>= 1) {
        if (tid < st) red[tid] += red[tid + st];
        __syncthreads();
    }
    float inv = 1.f / red[0];
#pragma unroll
    for (int i = 0; i < 4; i++) row[tid + i * 256] = vals[i] * inv;
}

// ---------------- SiLU(gate)*up ----------------
__global__ void silu_kernel(const float* __restrict__ gu, float* __restrict__ act)
{
    long i = (long)blockIdx.x * blockDim.x + threadIdx.x;
    if (i >= (long)SS * FF) return;
    long s = i / FF, f = i % FF;
    float g = gu[s * 2 * FF + f];
    float u = gu[s * 2 * FF + FF + f];
    act[i] = (g / (1.f + expf(-g))) * u;
}

// ---------------- lm_head: one warp per vocab row ----------------
__global__ void lmhead_kernel(const float* __restrict__ hl,
                              const float* __restrict__ w,
                              float* __restrict__ logits)
{
    int gtid = blockIdx.x * blockDim.x + threadIdx.x;
    int warp = gtid >> 5, lane = gtid & 31;
    if (warp >= VV) return;
    const float* wr = w + (size_t)warp * HID;
    float s = 0.f;
    for (int k = lane; k < HID; k += 32) s = fmaf(hl[k], wr[k], s);
#pragma unroll
    for (int off = 16; off > 0; off >>= 1)
        s += __shfl_down_sync(0xffffffffu, s, off);
    if (lane == 0) logits[warp] = s;
}

// ---------------- argmax + scalar outputs (as FLOATS: harness compares f32) --
__global__ void argmax_kernel(const float* __restrict__ lg, float* __restrict__ outf)
{
    __shared__ float bv[1024];
    __shared__ int   bi[1024];
    int tid = threadIdx.x;
    float best = -3.4e38f; int bidx = 0;
    for (int t = tid; t < VV; t += 1024) {
        float v = lg[t];
        if (v > best) { best = v; bidx = t; }
    }
    bv[tid] = best; bi[tid] = bidx; __syncthreads();
    for (int st = 512; st > 0; st >>= 1) {
        if (tid < st) {
            if (bv[tid + st] > bv[tid] ||
                (bv[tid + st] == bv[tid] && bi[tid + st] < bi[tid])) {
                bv[tid] = bv[tid + st]; bi[tid] = bi[tid + st];
            }
        }
        __syncthreads();
    }
    if (tid == 0) {
        outf[OUT_KVLEN] = (float)SS;    // kv_seq_len as float32
        outf[OUT_TOKEN] = (float)bi[0]; // token as float32
    }
}

// ---------------- launch ----------------
extern "C" void kernel_launch(void* const* d_in, const int* in_sizes, int n_in,
                              void* d_out, int out_size)
{
    // ---- robust binding: identify inputs by element count ----
    int i_ids = -1, i_mask = -1, i_eq = -1, i_lm = -1, i_esc = -1, i_ez = -1;
    int i_l1 = -1, i_l2 = -1, i_qkv = -1, i_ow = -1, i_gu = -1, i_dw = -1;
    int i_nw = -1, i_cos = -1, i_sin = -1;
    for (int i = 0; i < n_in; i++) {
        switch (in_sizes[i]) {
            case 1024:      i_ids = i; break;                       // input_ids (1,S)
            case 1:         i_mask = i; break;                      // mask_flag
            case 98304000:  if (i_eq < 0) i_eq = i; else i_lm = i; break;  // embed_q / lm_head_w
            case 32000:     if (i_esc < 0) i_esc = i; else i_ez = i; break; // embed_scale / embed_zero
            case 6144:      if (i_l1 < 0) i_l1 = i; else i_l2 = i; break;   // ln1_w / ln2_w
            case 31457280:  i_qkv = i; break;                       // qkv_w
            case 18874368:  i_ow = i; break;                        // o_w
            case 100663296: i_gu = i; break;                        // gate_up_w
            case 50331648:  i_dw = i; break;                        // down_w
            case 3072:      i_nw = i; break;                        // norm_w
            case 98304:     if (i_cos < 0) i_cos = i; else i_sin = i; break; // cos/sin
            default: break;
        }
    }
    const int*   ids    = (const int*)d_in[i_ids];
    const int*   maskf  = (i_mask >= 0) ? (const int*)d_in[i_mask] : nullptr;
    const void*  eq     = d_in[i_eq];
    const float* escale = (const float*)d_in[i_esc];
    const float* ezero  = (const float*)d_in[i_ez];
    const float* ln1    = (const float*)d_in[i_l1];
    const float* qkvw   = (const float*)d_in[i_qkv];
    const float* ow     = (const float*)d_in[i_ow];
    const float* ln2    = (const float*)d_in[i_l2];
    const float* guw    = (const float*)d_in[i_gu];
    const float* dw     = (const float*)d_in[i_dw];
    const float* normw  = (const float*)d_in[i_nw];
    const float* lmw    = (const float*)d_in[i_lm];
    const float* cosE   = (const float*)d_in[i_cos];
    const float* sinE   = (const float*)d_in[i_sin];
    float* out = (float*)d_out;

    float* scr = nullptr;
    cudaGetSymbolAddress((void**)&scr, g_scratch);
    float* hbuf   = scr + OFF_H;
    float* hn     = scr + OFF_HN;
    float* qkv    = scr + OFF_QKV;
    float* qb     = scr + OFF_Q;
    float* scores = scr + OFF_SC;
    float* ao     = scr + OFF_AO;
    float* gu     = scr + OFF_GU;
    float* act    = scr + OFF_ACT;
    float* hl     = scr + OFF_HL;
    float* logits = scr + OFF_LG;
    int*   flag   = (int*)(scr + OFF_FLAG);
    float* keys   = out + OUT_KEYS;
    float* valsb  = out + OUT_VALS;

    detect_dtype_kernel<<<1, 1>>>((const unsigned int*)eq, flag);
    embed_kernel<<<SS, 256>>>(ids, eq, escale, ezero, flag, hbuf);

    for (int l = 0; l < LL; l++) {
        float* lkeys = keys  + (size_t)l * KVH * DD * SS;
        float* lvals = valsb + (size_t)l * KVH * SS * DD;

        // hn = rms(h, ln1)
        rmsnorm_kernel<<<SS, 256>>>(hbuf, ln1 + (size_t)l * HID, hn, HID);
        // qkv = hn @ qkv_w^T   (N=5120, K=3072)
        sgemm_kernel<true, false><<<dim3(QKV_O / 128, SS / 128, 1), 256>>>(
            hn, HID, 0, qkvw + (size_t)l * QKV_O * HID, HID, 0, 1,
            qkv, QKV_O, 0, HID);
        // split + rope + scale; write K/V caches into d_out
        rope_split_kernel<<<(SS * QKV_O) / 256, 256>>>(qkv, cosE, sinE, qb, lkeys, lvals);
        // scores[h] = q[h] @ k[h/G]   (M=S, N=S, K=D), batched over 24 heads
        sgemm_kernel<false, false><<<dim3(SS / 128, SS / 128, HH), 256>>>(
            qb, DD, (long)SS * DD, lkeys, SS, (long)DD * SS, GG,
            scores, SS, (long)SS * SS, DD);
        // softmax with causal -128*mask
        softmax_kernel<<<dim3(SS, HH), 256>>>(scores, maskf);
        // ao[s, h*D+d] = P[h] @ v[h/G]   (M=S, N=D, K=S)
        sgemm_kernel<false, false><<<dim3(DD / 128, SS / 128, HH), 256>>>(
            scores, SS, (long)SS * SS, lvals, DD, (long)SS * DD, GG,
            ao, HID, (long)DD, SS);
        // h += ao @ o_w^T   (N=3072, K=3072), accumulate
        sgemm_kernel<true, true><<<dim3(HID / 128, SS / 128, 1), 256>>>(
            ao, HID, 0, ow + (size_t)l * HID * QP, QP, 0, 1,
            hbuf, HID, 0, QP);
        // hn = rms(h, ln2)
        rmsnorm_kernel<<<SS, 256>>>(hbuf, ln2 + (size_t)l * HID, hn, HID);
        // gu = hn @ gate_up_w^T  (N=16384, K=3072)
        sgemm_kernel<true, false><<<dim3(2 * FF / 128, SS / 128, 1), 256>>>(
            hn, HID, 0, guw + (size_t)l * 2 * FF * HID, HID, 0, 1,
            gu, 2 * FF, 0, HID);
        // act = silu(gate)*up
        silu_kernel<<<(SS * FF) / 256, 256>>>(gu, act);
        // h += act @ down_w^T   (N=3072, K=8192), accumulate
        sgemm_kernel<true, true><<<dim3(HID / 128, SS / 128, 1), 256>>>(
            act, FF, 0, dw + (size_t)l * HID * FF, FF, 0, 1,
            hbuf, HID, 0, FF);
    }

    // final: rms of last token, lm_head, argmax
    rmsnorm_kernel<<<1, 256>>>(hbuf + (size_t)(SS - 1) * HID, normw, hl, HID);
    lmhead_kernel<<<(VV * 32) / 256, 256>>>(hl, lmw, logits);
    argmax_kernel<<<1, 1024>>>(logits, (float*)d_out);
}

// round 5
// speedup vs baseline: 2.3278x; 2.3278x over previous
#include <cuda_runtime.h>
#include <cuda_bf16.h>
#include <cstdint>
#include <cmath>

// ---------------- problem constants ----------------
#define LL 2
#define HH 24
#define KVH 8
#define GG 3
#define DD 128
#define ROT 96
#define HALF 48
#define HID 3072
#define FF 8192
#define VV 32000
#define SS 1024
#define QP (HH*DD)          // 3072
#define KP (KVH*DD)         // 1024
#define QKV_O (QP + 2*KP)   // 5120
#define EPS 1e-6f
// SCALE = D^(-0.25)
__device__ __constant__ float SCALE_C = 0.29730177875068026f;

// ---------------- scratch (single device symbol, no allocations) -----------
#define OFF_H      0ull
#define OFF_HN     (OFF_H   + (size_t)SS*HID)
#define OFF_QKV    (OFF_HN  + (size_t)SS*HID)
#define OFF_Q      (OFF_QKV + (size_t)SS*QKV_O)
#define OFF_SC     (OFF_Q   + (size_t)HH*SS*DD)
#define OFF_AO     (OFF_SC  + (size_t)HH*SS*SS)
#define OFF_GU     (OFF_AO  + (size_t)SS*HID)
#define OFF_ACT    (OFF_GU  + (size_t)SS*2*FF)
#define OFF_HL     (OFF_ACT + (size_t)SS*FF)
#define OFF_LG     (OFF_HL  + (size_t)HID)
#define OFF_FLAG   (OFF_LG  + (size_t)VV)
#define SCRATCH_TOTAL (OFF_FLAG + 16)

__device__ float g_scratch[SCRATCH_TOTAL];

// output layout (4-byte elements)
#define OUT_KEYS   0ull
#define OUT_VALS   ((size_t)LL*KVH*DD*SS)
#define OUT_KVLEN  (2ull*LL*KVH*DD*SS)
#define OUT_TOKEN  (OUT_KVLEN + 1)

// ---------------- dtype probe for embed_q ----------------
// mode: 0 = uint8, 1 = int32, 2 = float32, 3 = bfloat16
__global__ void detect_dtype_kernel(const unsigned int* __restrict__ w,
                                    int* __restrict__ mode)
{
    bool all_small = true, all_f32 = true, all_bf16 = true;
    for (int i = 0; i < 64; i++) {
        unsigned int x = w[i];
        if (x > 255u) all_small = false;
        float f = __uint_as_float(x);
        if (!(f >= 0.f && f <= 255.f && f == rintf(f))) all_f32 = false;
        float f0 = __uint_as_float(x << 16);
        float f1 = __uint_as_float(x & 0xFFFF0000u);
        if (!(f0 >= 0.f && f0 <= 255.f && f0 == rintf(f0) &&
              f1 >= 0.f && f1 <= 255.f && f1 == rintf(f1))) all_bf16 = false;
    }
    *mode = all_small ? 1 : (all_f32 ? 2 : (all_bf16 ? 3 : 0));
}

// ---------------- embed ----------------
__global__ void embed_kernel(const int* __restrict__ ids,
                             const void* __restrict__ eq,
                             const float* __restrict__ escale,
                             const float* __restrict__ ezero,
                             const int* __restrict__ modep,
                             float* __restrict__ h)
{
    int s = blockIdx.x;
    int id = ids[s];
    float sc = escale[id], z = ezero[id];
    float* out = h + (size_t)s * HID;
    int mode = *modep;
    if (mode == 1) {
        const int* row = (const int*)eq + (size_t)id * HID;
        for (int j = threadIdx.x; j < HID; j += blockDim.x)
            out[j] = (float)row[j] * sc + z;
    } else if (mode == 2) {
        const float* row = (const float*)eq + (size_t)id * HID;
        for (int j = threadIdx.x; j < HID; j += blockDim.x)
            out[j] = row[j] * sc + z;
    } else if (mode == 3) {
        const unsigned short* row = (const unsigned short*)eq + (size_t)id * HID;
        for (int j = threadIdx.x; j < HID; j += blockDim.x)
            out[j] = __uint_as_float(((unsigned int)row[j]) << 16) * sc + z;
    } else {
        const unsigned char* row = (const unsigned char*)eq + (size_t)id * HID;
        for (int j = threadIdx.x; j < HID; j += blockDim.x)
            out[j] = (float)row[j] * sc + z;
    }
}

// ---------------- RMSNorm ----------------
__global__ void rmsnorm_kernel(const float* __restrict__ in,
                               const float* __restrict__ w,
                               float* __restrict__ out, int n)
{
    __shared__ float red[256];
    int row = blockIdx.x;
    const float* x = in + (size_t)row * n;
    float* y = out + (size_t)row * n;
    float s = 0.f;
    for (int i = threadIdx.x; i < n; i += 256) { float v = x[i]; s += v * v; }
    red[threadIdx.x] = s; __syncthreads();
    for (int st = 128; st > 0; st >>= 1) {
        if (threadIdx.x < st) red[threadIdx.x] += red[threadIdx.x + st];
        __syncthreads();
    }
    float inv = rsqrtf(red[0] / (float)n + EPS);
    for (int i = threadIdx.x; i < n; i += 256)
        y[i] = w[i] * x[i] * inv;
}

// ---------------- tf32 helpers ----------------
__device__ __forceinline__ unsigned cvt_tf32(float x) {
    unsigned r;
    asm("cvt.rna.tf32.f32 %0, %1;" : "=r"(r) : "f"(x));
    return r;
}

__device__ __forceinline__ void mma_tf32(float* d, const unsigned* a, const unsigned* b) {
    asm("mma.sync.aligned.m16n8k8.row.col.f32.tf32.tf32.f32 "
        "{%0,%1,%2,%3}, {%4,%5,%6,%7}, {%8,%9}, {%0,%1,%2,%3};"
        : "+f"(d[0]), "+f"(d[1]), "+f"(d[2]), "+f"(d[3])
        : "r"(a[0]), "r"(a[1]), "r"(a[2]), "r"(a[3]),
          "r"(b[0]), "r"(b[1]));
}

// ---------------- tensor-core tf32 batched GEMM ----------------
// C[M,N] (z-batched) = A[M,K] * B ; B is (N,K) row-major if TRANSB else (K,N).
// B batch index = z / gdivB. CTA tile 128x128, K-step 16, 8 warps (2x4),
// warp tile 64x32 via m16n8k8 tf32 mma. Requires M%128==0, N%128==0, K%16==0.
template<bool TRANSB, bool ACC>
__global__ __launch_bounds__(256, 2) void tgemm_kernel(
    const float* __restrict__ A, int lda, long sA,
    const float* __restrict__ B, int ldb, long sB, int gdivB,
    float* __restrict__ C, int ldc, long sC,
    int K)
{
    __shared__ unsigned As[16][136];   // [k][m], pad 136 for conflict-free frag loads
    __shared__ unsigned Bs[16][136];   // [k][n]
    int bz = blockIdx.z;
    A += (long)bz * sA;
    B += (long)(bz / gdivB) * sB;
    C += (long)bz * sC;
    int m0 = blockIdx.y * 128, n0 = blockIdx.x * 128;
    int tid = threadIdx.x;
    int wid = tid >> 5, lane = tid & 31;
    int wm = (wid >> 2) * 64;          // warp m-offset (2 warps in m)
    int wn = (wid & 3) * 32;           // warp n-offset (4 warps in n)
    int g = lane >> 2, tig = lane & 3; // groupID, threadID-in-group

    float acc[4][4][4];
#pragma unroll
    for (int mi = 0; mi < 4; mi++)
#pragma unroll
        for (int ni = 0; ni < 4; ni++)
#pragma unroll
            for (int r = 0; r < 4; r++) acc[mi][ni][r] = 0.f;

    // global load mapping (A and TRANSB-B): row = tid/4 (+64), cols k0+(tid%4)*4
    int arow = tid >> 2;
    int acol = (tid & 3) * 4;
    // !TRANSB B: row = tid/32 (+8), col = (tid%32)*4
    int brow = tid >> 5;
    int bcol = (tid & 31) * 4;

    for (int k0 = 0; k0 < K; k0 += 16) {
        // ---- stage A tile (128x16) ----
        {
            float4 v0 = *(const float4*)(A + (long)(m0 + arow) * lda + k0 + acol);
            float4 v1 = *(const float4*)(A + (long)(m0 + arow + 64) * lda + k0 + acol);
            As[acol + 0][arow] = cvt_tf32(v0.x); As[acol + 1][arow] = cvt_tf32(v0.y);
            As[acol + 2][arow] = cvt_tf32(v0.z); As[acol + 3][arow] = cvt_tf32(v0.w);
            As[acol + 0][arow + 64] = cvt_tf32(v1.x); As[acol + 1][arow + 64] = cvt_tf32(v1.y);
            As[acol + 2][arow + 64] = cvt_tf32(v1.z); As[acol + 3][arow + 64] = cvt_tf32(v1.w);
        }
        // ---- stage B tile (16 x 128 in [k][n]) ----
        if (TRANSB) {
            float4 v0 = *(const float4*)(B + (long)(n0 + arow) * ldb + k0 + acol);
            float4 v1 = *(const float4*)(B + (long)(n0 + arow + 64) * ldb + k0 + acol);
            Bs[acol + 0][arow] = cvt_tf32(v0.x); Bs[acol + 1][arow] = cvt_tf32(v0.y);
            Bs[acol + 2][arow] = cvt_tf32(v0.z); Bs[acol + 3][arow] = cvt_tf32(v0.w);
            Bs[acol + 0][arow + 64] = cvt_tf32(v1.x); Bs[acol + 1][arow + 64] = cvt_tf32(v1.y);
            Bs[acol + 2][arow + 64] = cvt_tf32(v1.z); Bs[acol + 3][arow + 64] = cvt_tf32(v1.w);
        } else {
#pragma unroll
            for (int rr = 0; rr < 2; rr++) {
                int r = brow + rr * 8;
                float4 v = *(const float4*)(B + (long)(k0 + r) * ldb + n0 + bcol);
                uint4 u;
                u.x = cvt_tf32(v.x); u.y = cvt_tf32(v.y);
                u.z = cvt_tf32(v.z); u.w = cvt_tf32(v.w);
                *(uint4*)&Bs[r][bcol] = u;
            }
        }
        __syncthreads();

#pragma unroll
        for (int kk = 0; kk < 16; kk += 8) {
            unsigned afr[4][4];
            unsigned bfr[4][2];
#pragma unroll
            for (int mi = 0; mi < 4; mi++) {
                int mr = wm + mi * 16 + g;
                afr[mi][0] = As[kk + tig][mr];
                afr[mi][1] = As[kk + tig][mr + 8];
                afr[mi][2] = As[kk + tig + 4][mr];
                afr[mi][3] = As[kk + tig + 4][mr + 8];
            }
#pragma unroll
            for (int ni = 0; ni < 4; ni++) {
                int nc = wn + ni * 8 + g;
                bfr[ni][0] = Bs[kk + tig][nc];
                bfr[ni][1] = Bs[kk + tig + 4][nc];
            }
#pragma unroll
            for (int mi = 0; mi < 4; mi++)
#pragma unroll
                for (int ni = 0; ni < 4; ni++)
                    mma_tf32(acc[mi][ni], afr[mi], bfr[ni]);
        }
        __syncthreads();
    }

    // ---- epilogue ----
#pragma unroll
    for (int mi = 0; mi < 4; mi++) {
        int row = m0 + wm + mi * 16 + g;
#pragma unroll
        for (int ni = 0; ni < 4; ni++) {
            int col = n0 + wn + ni * 8 + 2 * tig;
            float2* p0 = (float2*)(C + (long)row * ldc + col);
            float2* p1 = (float2*)(C + (long)(row + 8) * ldc + col);
            if (ACC) {
                float2 o0 = *p0, o1 = *p1;
                o0.x += acc[mi][ni][0]; o0.y += acc[mi][ni][1];
                o1.x += acc[mi][ni][2]; o1.y += acc[mi][ni][3];
                *p0 = o0; *p1 = o1;
            } else {
                *p0 = make_float2(acc[mi][ni][0], acc[mi][ni][1]);
                *p1 = make_float2(acc[mi][ni][2], acc[mi][ni][3]);
            }
        }
    }
}

// ---------------- split qkv + rope + scale; write K/V caches to d_out -------
__global__ void rope_split_kernel(const float* __restrict__ qkv,
                                  const float* __restrict__ cosE,
                                  const float* __restrict__ sinE,
                                  float* __restrict__ qout,     // [H][S][D]
                                  float* __restrict__ keys,     // [KV][D][S]
                                  float* __restrict__ vals)     // [KV][S][D]
{
    long idx = (long)blockIdx.x * blockDim.x + threadIdx.x;
    if (idx >= (long)SS * QKV_O) return;
    int s = (int)(idx / QKV_O);
    int c = (int)(idx % QKV_O);
    float v = qkv[idx];
    float scale = SCALE_C;
    if (c < QP) {
        int hh = c / DD, d = c % DD;
        float val = v * scale;
        if (d < ROT) {
            int pd = (d < HALF) ? d + HALF : d - HALF;
            float partner = qkv[(long)s * QKV_O + hh * DD + pd] * scale;
            float r = (d < HALF) ? -partner : partner;
            val = val * cosE[s * ROT + d] + r * sinE[s * ROT + d];
        }
        qout[((size_t)hh * SS + s) * DD + d] = val;
    } else if (c < QP + KP) {
        int kc = c - QP;
        int kv = kc / DD, d = kc % DD;
        float val = v * scale;
        if (d < ROT) {
            int pd = (d < HALF) ? d + HALF : d - HALF;
            float partner = qkv[(long)s * QKV_O + QP + kv * DD + pd] * scale;
            float r = (d < HALF) ? -partner : partner;
            val = val * cosE[s * ROT + d] + r * sinE[s * ROT + d];
        }
        keys[((size_t)kv * DD + d) * SS + s] = val;
    } else {
        int vc = c - QP - KP;
        int kv = vc / DD, d = vc % DD;
        vals[((size_t)kv * SS + s) * DD + d] = v;
    }
}

// ---------------- softmax with causal additive mask -128*mask_flag ----------
__global__ void softmax_kernel(float* __restrict__ sc, const int* __restrict__ maskf)
{
    __shared__ float red[256];
    int s = blockIdx.x, h = blockIdx.y;
    float* row = sc + ((size_t)h * SS + s) * SS;
    int mflag = maskf ? *maskf : 1;
    float mf = -128.f * (float)mflag;
    int tid = threadIdx.x;
    float vals[4];
    float lmax = -3.4e38f;
#pragma unroll
    for (int i = 0; i < 4; i++) {
        int t = tid + i * 256;
        float x = row[t] + ((t <= s) ? 0.f : mf);
        vals[i] = x;
        lmax = fmaxf(lmax, x);
    }
    red[tid] = lmax; __syncthreads();
    for (int st = 128; st > 0; st >>= 1) {
        if (tid < st) red[tid] = fmaxf(red[tid], red[tid + st]);
        __syncthreads();
    }
    float mx = red[0]; __syncthreads();
    float lsum = 0.f;
#pragma unroll
    for (int i = 0; i < 4; i++) { vals[i] = expf(vals[i] - mx); lsum += vals[i]; }
    red[tid] = lsum; __syncthreads();
    for (int st = 128; st > 0; st >>= 1) {
        if (tid < st) red[tid] += red[tid + st];
        __syncthreads();
    }
    float inv = 1.f / red[0];
#pragma unroll
    for (int i = 0; i < 4; i++) row[tid + i * 256] = vals[i] * inv;
}

// ---------------- SiLU(gate)*up ----------------
__global__ void silu_kernel(const float* __restrict__ gu, float* __restrict__ act)
{
    long i = (long)blockIdx.x * blockDim.x + threadIdx.x;
    if (i >= (long)SS * FF) return;
    long s = i / FF, f = i % FF;
    float g = gu[s * 2 * FF + f];
    float u = gu[s * 2 * FF + FF + f];
    act[i] = (g / (1.f + expf(-g))) * u;
}

// ---------------- lm_head: one warp per vocab row ----------------
__global__ void lmhead_kernel(const float* __restrict__ hl,
                              const float* __restrict__ w,
                              float* __restrict__ logits)
{
    int gtid = blockIdx.x * blockDim.x + threadIdx.x;
    int warp = gtid >> 5, lane = gtid & 31;
    if (warp >= VV) return;
    const float* wr = w + (size_t)warp * HID;
    float s = 0.f;
    for (int k = lane; k < HID; k += 32) s = fmaf(hl[k], wr[k], s);
#pragma unroll
    for (int off = 16; off > 0; off >>= 1)
        s += __shfl_down_sync(0xffffffffu, s, off);
    if (lane == 0) logits[warp] = s;
}

// ---------------- argmax + scalar outputs (floats; harness compares f32) ----
__global__ void argmax_kernel(const float* __restrict__ lg, float* __restrict__ outf)
{
    __shared__ float bv[1024];
    __shared__ int   bi[1024];
    int tid = threadIdx.x;
    float best = -3.4e38f; int bidx = 0;
    for (int t = tid; t < VV; t += 1024) {
        float v = lg[t];
        if (v > best) { best = v; bidx = t; }
    }
    bv[tid] = best; bi[tid] = bidx; __syncthreads();
    for (int st = 512; st > 0; st >>= 1) {
        if (tid < st) {
            if (bv[tid + st] > bv[tid] ||
                (bv[tid + st] == bv[tid] && bi[tid + st] < bi[tid])) {
                bv[tid] = bv[tid + st]; bi[tid] = bi[tid + st];
            }
        }
        __syncthreads();
    }
    if (tid == 0) {
        outf[OUT_KVLEN] = (float)SS;
        outf[OUT_TOKEN] = (float)bi[0];
    }
}

// ---------------- launch ----------------
extern "C" void kernel_launch(void* const* d_in, const int* in_sizes, int n_in,
                              void* d_out, int out_size)
{
    // ---- robust binding: identify inputs by element count ----
    int i_ids = -1, i_mask = -1, i_eq = -1, i_lm = -1, i_esc = -1, i_ez = -1;
    int i_l1 = -1, i_l2 = -1, i_qkv = -1, i_ow = -1, i_gu = -1, i_dw = -1;
    int i_nw = -1, i_cos = -1, i_sin = -1;
    for (int i = 0; i < n_in; i++) {
        switch (in_sizes[i]) {
            case 1024:      i_ids = i; break;
            case 1:         i_mask = i; break;
            case 98304000:  if (i_eq < 0) i_eq = i; else i_lm = i; break;
            case 32000:     if (i_esc < 0) i_esc = i; else i_ez = i; break;
            case 6144:      if (i_l1 < 0) i_l1 = i; else i_l2 = i; break;
            case 31457280:  i_qkv = i; break;
            case 18874368:  i_ow = i; break;
            case 100663296: i_gu = i; break;
            case 50331648:  i_dw = i; break;
            case 3072:      i_nw = i; break;
            case 98304:     if (i_cos < 0) i_cos = i; else i_sin = i; break;
            default: break;
        }
    }
    const int*   ids    = (const int*)d_in[i_ids];
    const int*   maskf  = (i_mask >= 0) ? (const int*)d_in[i_mask] : nullptr;
    const void*  eq     = d_in[i_eq];
    const float* escale = (const float*)d_in[i_esc];
    const float* ezero  = (const float*)d_in[i_ez];
    const float* ln1    = (const float*)d_in[i_l1];
    const float* qkvw   = (const float*)d_in[i_qkv];
    const float* ow     = (const float*)d_in[i_ow];
    const float* ln2    = (const float*)d_in[i_l2];
    const float* guw    = (const float*)d_in[i_gu];
    const float* dw     = (const float*)d_in[i_dw];
    const float* normw  = (const float*)d_in[i_nw];
    const float* lmw    = (const float*)d_in[i_lm];
    const float* cosE   = (const float*)d_in[i_cos];
    const float* sinE   = (const float*)d_in[i_sin];
    float* out = (float*)d_out;

    float* scr = nullptr;
    cudaGetSymbolAddress((void**)&scr, g_scratch);
    float* hbuf   = scr + OFF_H;
    float* hn     = scr + OFF_HN;
    float* qkv    = scr + OFF_QKV;
    float* qb     = scr + OFF_Q;
    float* scores = scr + OFF_SC;
    float* ao     = scr + OFF_AO;
    float* gu     = scr + OFF_GU;
    float* act    = scr + OFF_ACT;
    float* hl     = scr + OFF_HL;
    float* logits = scr + OFF_LG;
    int*   flag   = (int*)(scr + OFF_FLAG);
    float* keys   = out + OUT_KEYS;
    float* valsb  = out + OUT_VALS;

    detect_dtype_kernel<<<1, 1>>>((const unsigned int*)eq, flag);
    embed_kernel<<<SS, 256>>>(ids, eq, escale, ezero, flag, hbuf);

    for (int l = 0; l < LL; l++) {
        float* lkeys = keys  + (size_t)l * KVH * DD * SS;
        float* lvals = valsb + (size_t)l * KVH * SS * DD;

        // hn = rms(h, ln1)
        rmsnorm_kernel<<<SS, 256>>>(hbuf, ln1 + (size_t)l * HID, hn, HID);
        // qkv = hn @ qkv_w^T   (N=5120, K=3072)
        tgemm_kernel<true, false><<<dim3(QKV_O / 128, SS / 128, 1), 256>>>(
            hn, HID, 0, qkvw + (size_t)l * QKV_O * HID, HID, 0, 1,
            qkv, QKV_O, 0, HID);
        // split + rope + scale; write K/V caches into d_out
        rope_split_kernel<<<(SS * QKV_O) / 256, 256>>>(qkv, cosE, sinE, qb, lkeys, lvals);
        // scores[h] = q[h] @ k[h/G]   (M=S, N=S, K=D), batched over 24 heads
        tgemm_kernel<false, false><<<dim3(SS / 128, SS / 128, HH), 256>>>(
            qb, DD, (long)SS * DD, lkeys, SS, (long)DD * SS, GG,
            scores, SS, (long)SS * SS, DD);
        // softmax with causal -128*mask
        softmax_kernel<<<dim3(SS, HH), 256>>>(scores, maskf);
        // ao[s, h*D+d] = P[h] @ v[h/G]   (M=S, N=D, K=S)
        tgemm_kernel<false, false><<<dim3(DD / 128, SS / 128, HH), 256>>>(
            scores, SS, (long)SS * SS, lvals, DD, (long)SS * DD, GG,
            ao, HID, (long)DD, SS);
        // h += ao @ o_w^T   (N=3072, K=3072), accumulate
        tgemm_kernel<true, true><<<dim3(HID / 128, SS / 128, 1), 256>>>(
            ao, HID, 0, ow + (size_t)l * HID * QP, QP, 0, 1,
            hbuf, HID, 0, QP);
        // hn = rms(h, ln2)
        rmsnorm_kernel<<<SS, 256>>>(hbuf, ln2 + (size_t)l * HID, hn, HID);
        // gu = hn @ gate_up_w^T  (N=16384, K=3072)
        tgemm_kernel<true, false><<<dim3(2 * FF / 128, SS / 128, 1), 256>>>(
            hn, HID, 0, guw + (size_t)l * 2 * FF * HID, HID, 0, 1,
            gu, 2 * FF, 0, HID);
        // act = silu(gate)*up
        silu_kernel<<<(SS * FF) / 256, 256>>>(gu, act);
        // h += act @ down_w^T   (N=3072, K=8192), accumulate
        tgemm_kernel<true, true><<<dim3(HID / 128, SS / 128, 1), 256>>>(
            act, FF, 0, dw + (size_t)l * HID * FF, FF, 0, 1,
            hbuf, HID, 0, FF);
    }

    // final: rms of last token, lm_head, argmax
    rmsnorm_kernel<<<1, 256>>>(hbuf + (size_t)(SS - 1) * HID, normw, hl, HID);
    lmhead_kernel<<<(VV * 32) / 256, 256>>>(hl, lmw, logits);
    argmax_kernel<<<1, 1024>>>(logits, (float*)d_out);
}

// round 6
// speedup vs baseline: 3.2806x; 1.4094x over previous
#include <cuda_runtime.h>
#include <cuda_bf16.h>
#include <cstdint>
#include <cmath>

// ---------------- problem constants ----------------
#define LL 2
#define HH 24
#define KVH 8
#define GG 3
#define DD 128
#define ROT 96
#define HALF 48
#define HID 3072
#define FF 8192
#define VV 32000
#define SS 1024
#define QP (HH*DD)          // 3072
#define KP (KVH*DD)         // 1024
#define QKV_O (QP + 2*KP)   // 5120
#define EPS 1e-6f
// SCALE = D^(-0.25)
__device__ __constant__ float SCALE_C = 0.29730177875068026f;

// ---------------- scratch (single device symbol, no allocations) -----------
#define OFF_H      0ull
#define OFF_HN     (OFF_H   + (size_t)SS*HID)
#define OFF_QKV    (OFF_HN  + (size_t)SS*HID)
#define OFF_Q      (OFF_QKV + (size_t)SS*QKV_O)
#define OFF_SC     (OFF_Q   + (size_t)HH*SS*DD)
#define OFF_AO     (OFF_SC  + (size_t)HH*SS*SS)
#define OFF_GU     (OFF_AO  + (size_t)SS*HID)
#define OFF_ACT    (OFF_GU  + (size_t)SS*2*FF)
#define OFF_HL     (OFF_ACT + (size_t)SS*FF)
#define OFF_LG     (OFF_HL  + (size_t)HID)
#define OFF_FLAG   (OFF_LG  + (size_t)VV)
#define SCRATCH_TOTAL (OFF_FLAG + 16)

__device__ float g_scratch[SCRATCH_TOTAL];

// output layout (4-byte elements)
#define OUT_KEYS   0ull
#define OUT_VALS   ((size_t)LL*KVH*DD*SS)
#define OUT_KVLEN  (2ull*LL*KVH*DD*SS)
#define OUT_TOKEN  (OUT_KVLEN + 1)

// ---------------- dtype probe for embed_q ----------------
__global__ void detect_dtype_kernel(const unsigned int* __restrict__ w,
                                    int* __restrict__ mode)
{
    bool all_small = true, all_f32 = true, all_bf16 = true;
    for (int i = 0; i < 64; i++) {
        unsigned int x = w[i];
        if (x > 255u) all_small = false;
        float f = __uint_as_float(x);
        if (!(f >= 0.f && f <= 255.f && f == rintf(f))) all_f32 = false;
        float f0 = __uint_as_float(x << 16);
        float f1 = __uint_as_float(x & 0xFFFF0000u);
        if (!(f0 >= 0.f && f0 <= 255.f && f0 == rintf(f0) &&
              f1 >= 0.f && f1 <= 255.f && f1 == rintf(f1))) all_bf16 = false;
    }
    *mode = all_small ? 1 : (all_f32 ? 2 : (all_bf16 ? 3 : 0));
}

// ---------------- embed ----------------
__global__ void embed_kernel(const int* __restrict__ ids,
                             const void* __restrict__ eq,
                             const float* __restrict__ escale,
                             const float* __restrict__ ezero,
                             const int* __restrict__ modep,
                             float* __restrict__ h)
{
    int s = blockIdx.x;
    int id = ids[s];
    float sc = escale[id], z = ezero[id];
    float* out = h + (size_t)s * HID;
    int mode = *modep;
    if (mode == 1) {
        const int* row = (const int*)eq + (size_t)id * HID;
        for (int j = threadIdx.x; j < HID; j += blockDim.x)
            out[j] = (float)row[j] * sc + z;
    } else if (mode == 2) {
        const float* row = (const float*)eq + (size_t)id * HID;
        for (int j = threadIdx.x; j < HID; j += blockDim.x)
            out[j] = row[j] * sc + z;
    } else if (mode == 3) {
        const unsigned short* row = (const unsigned short*)eq + (size_t)id * HID;
        for (int j = threadIdx.x; j < HID; j += blockDim.x)
            out[j] = __uint_as_float(((unsigned int)row[j]) << 16) * sc + z;
    } else {
        const unsigned char* row = (const unsigned char*)eq + (size_t)id * HID;
        for (int j = threadIdx.x; j < HID; j += blockDim.x)
            out[j] = (float)row[j] * sc + z;
    }
}

// ---------------- RMSNorm ----------------
__global__ void rmsnorm_kernel(const float* __restrict__ in,
                               const float* __restrict__ w,
                               float* __restrict__ out, int n)
{
    __shared__ float red[256];
    int row = blockIdx.x;
    const float* x = in + (size_t)row * n;
    float* y = out + (size_t)row * n;
    float s = 0.f;
    for (int i = threadIdx.x; i < n; i += 256) { float v = x[i]; s += v * v; }
    red[threadIdx.x] = s; __syncthreads();
    for (int st = 128; st > 0; st >>= 1) {
        if (threadIdx.x < st) red[threadIdx.x] += red[threadIdx.x + st];
        __syncthreads();
    }
    float inv = rsqrtf(red[0] / (float)n + EPS);
    for (int i = threadIdx.x; i < n; i += 256)
        y[i] = w[i] * x[i] * inv;
}

// ---------------- tf32 / cp.async helpers ----------------
__device__ __forceinline__ unsigned cvt_tf32(float x) {
    unsigned r;
    asm("cvt.rna.tf32.f32 %0, %1;" : "=r"(r) : "f"(x));
    return r;
}

__device__ __forceinline__ void mma_tf32(float* d, const unsigned* a, const unsigned* b) {
    asm("mma.sync.aligned.m16n8k8.row.col.f32.tf32.tf32.f32 "
        "{%0,%1,%2,%3}, {%4,%5,%6,%7}, {%8,%9}, {%0,%1,%2,%3};"
        : "+f"(d[0]), "+f"(d[1]), "+f"(d[2]), "+f"(d[3])
        : "r"(a[0]), "r"(a[1]), "r"(a[2]), "r"(a[3]),
          "r"(b[0]), "r"(b[1]));
}

__device__ __forceinline__ void cp_async16(float* dst, const float* src) {
    unsigned d = (unsigned)__cvta_generic_to_shared(dst);
    asm volatile("cp.async.cg.shared.global [%0], [%1], 16;\n" :: "r"(d), "l"(src));
}
__device__ __forceinline__ void cp_commit() {
    asm volatile("cp.async.commit_group;\n");
}
__device__ __forceinline__ void cp_wait1() {
    asm volatile("cp.async.wait_group 1;\n");
}
__device__ __forceinline__ void cp_wait0() {
    asm volatile("cp.async.wait_group 0;\n");
}

// ---------------- tensor-core tf32 batched GEMM, 2-stage cp.async ----------
// C[M,N] (z-batched) = A[M,K] * B ; B is (N,K) row-major if TRANSB else (K,N).
// B batch index = z / gdivB. CTA tile 128x128, K-step 16, 8 warps (2x4),
// warp tile 64x32 via m16n8k8 tf32 mma. Raw fp32 staged; cvt.rna at frag load.
// Requires M%128==0, N%128==0, K%16==0.
#define APAD 20     // A (and TRANSB-B) smem row stride in floats
#define BPAD 136    // !TRANSB-B smem row stride in floats
template<bool TRANSB, bool ACC>
__global__ __launch_bounds__(256, 2) void tgemm_kernel(
    const float* __restrict__ A, int lda, long sA,
    const float* __restrict__ B, int ldb, long sB, int gdivB,
    float* __restrict__ C, int ldc, long sC,
    int K)
{
    constexpr int ASZ = 128 * APAD;                       // 2560 floats
    constexpr int BSZ = TRANSB ? 128 * APAD : 16 * BPAD;  // 2560 / 2176
    __shared__ __align__(16) float smem[2 * (ASZ + BSZ)];

    int bz = blockIdx.z;
    A += (long)bz * sA;
    B += (long)(bz / gdivB) * sB;
    C += (long)bz * sC;
    int m0 = blockIdx.y * 128, n0 = blockIdx.x * 128;
    int tid = threadIdx.x;
    int wid = tid >> 5, lane = tid & 31;
    int wm = (wid >> 2) * 64;          // warp m-offset (2 warps in m)
    int wn = (wid & 3) * 32;           // warp n-offset (4 warps in n)
    int g = lane >> 2, tig = lane & 3; // groupID, threadID-in-group

    float acc[4][4][4];
#pragma unroll
    for (int mi = 0; mi < 4; mi++)
#pragma unroll
        for (int ni = 0; ni < 4; ni++)
#pragma unroll
            for (int r = 0; r < 4; r++) acc[mi][ni][r] = 0.f;

    int nk = K >> 4;

    // prefetch lambda-free inline: stage s covers k0 = it*16
    // A tile: 128 rows x 16 floats, chunks of 16B: 512 chunks, 2 per thread
    // B TRANSB: same shape; B !TRANSB: 16 rows x 128 floats, 512 chunks
    int c0 = tid, c1 = tid + 256;

#define PREFETCH(s, k0)                                                         \
    {                                                                           \
        float* as = smem + (s) * (ASZ + BSZ);                                   \
        float* bs = as + ASZ;                                                   \
        {                                                                       \
            int r = c0 >> 2, cf = (c0 & 3) * 4;                                 \
            cp_async16(as + r * APAD + cf, A + (long)(m0 + r) * lda + (k0) + cf);\
            r = c1 >> 2; cf = (c1 & 3) * 4;                                     \
            cp_async16(as + r * APAD + cf, A + (long)(m0 + r) * lda + (k0) + cf);\
        }                                                                       \
        if (TRANSB) {                                                           \
            int r = c0 >> 2, cf = (c0 & 3) * 4;                                 \
            cp_async16(bs + r * APAD + cf, B + (long)(n0 + r) * ldb + (k0) + cf);\
            r = c1 >> 2; cf = (c1 & 3) * 4;                                     \
            cp_async16(bs + r * APAD + cf, B + (long)(n0 + r) * ldb + (k0) + cf);\
        } else {                                                                \
            int r = c0 >> 5, cf = (c0 & 31) * 4;                                \
            cp_async16(bs + r * BPAD + cf, B + (long)((k0) + r) * ldb + n0 + cf);\
            r = c1 >> 5; cf = (c1 & 31) * 4;                                    \
            cp_async16(bs + r * BPAD + cf, B + (long)((k0) + r) * ldb + n0 + cf);\
        }                                                                       \
        cp_commit();                                                            \
    }

    PREFETCH(0, 0);

    for (int it = 0; it < nk; it++) {
        if (it + 1 < nk) {
            PREFETCH((it + 1) & 1, (it + 1) << 4);
            cp_wait1();
        } else {
            cp_wait0();
        }
        __syncthreads();

        const float* as = smem + (it & 1) * (ASZ + BSZ);
        const float* bs = as + ASZ;

#pragma unroll
        for (int kk = 0; kk < 16; kk += 8) {
            unsigned afr[4][4];
            unsigned bfr[4][2];
#pragma unroll
            for (int mi = 0; mi < 4; mi++) {
                int mr = wm + mi * 16 + g;
                afr[mi][0] = cvt_tf32(as[mr * APAD + kk + tig]);
                afr[mi][1] = cvt_tf32(as[(mr + 8) * APAD + kk + tig]);
                afr[mi][2] = cvt_tf32(as[mr * APAD + kk + tig + 4]);
                afr[mi][3] = cvt_tf32(as[(mr + 8) * APAD + kk + tig + 4]);
            }
#pragma unroll
            for (int ni = 0; ni < 4; ni++) {
                int nc = wn + ni * 8 + g;
                if (TRANSB) {
                    bfr[ni][0] = cvt_tf32(bs[nc * APAD + kk + tig]);
                    bfr[ni][1] = cvt_tf32(bs[nc * APAD + kk + tig + 4]);
                } else {
                    bfr[ni][0] = cvt_tf32(bs[(kk + tig) * BPAD + nc]);
                    bfr[ni][1] = cvt_tf32(bs[(kk + tig + 4) * BPAD + nc]);
                }
            }
#pragma unroll
            for (int mi = 0; mi < 4; mi++)
#pragma unroll
                for (int ni = 0; ni < 4; ni++)
                    mma_tf32(acc[mi][ni], afr[mi], bfr[ni]);
        }
        __syncthreads();
    }

    // ---- epilogue ----
#pragma unroll
    for (int mi = 0; mi < 4; mi++) {
        int row = m0 + wm + mi * 16 + g;
#pragma unroll
        for (int ni = 0; ni < 4; ni++) {
            int col = n0 + wn + ni * 8 + 2 * tig;
            float2* p0 = (float2*)(C + (long)row * ldc + col);
            float2* p1 = (float2*)(C + (long)(row + 8) * ldc + col);
            if (ACC) {
                float2 o0 = *p0, o1 = *p1;
                o0.x += acc[mi][ni][0]; o0.y += acc[mi][ni][1];
                o1.x += acc[mi][ni][2]; o1.y += acc[mi][ni][3];
                *p0 = o0; *p1 = o1;
            } else {
                *p0 = make_float2(acc[mi][ni][0], acc[mi][ni][1]);
                *p1 = make_float2(acc[mi][ni][2], acc[mi][ni][3]);
            }
        }
    }
}
#undef PREFETCH

// ---------------- split qkv + rope + scale; write K/V caches to d_out -------
__global__ void rope_split_kernel(const float* __restrict__ qkv,
                                  const float* __restrict__ cosE,
                                  const float* __restrict__ sinE,
                                  float* __restrict__ qout,     // [H][S][D]
                                  float* __restrict__ keys,     // [KV][D][S]
                                  float* __restrict__ vals)     // [KV][S][D]
{
    long idx = (long)blockIdx.x * blockDim.x + threadIdx.x;
    if (idx >= (long)SS * QKV_O) return;
    int s = (int)(idx / QKV_O);
    int c = (int)(idx % QKV_O);
    float v = qkv[idx];
    float scale = SCALE_C;
    if (c < QP) {
        int hh = c / DD, d = c % DD;
        float val = v * scale;
        if (d < ROT) {
            int pd = (d < HALF) ? d + HALF : d - HALF;
            float partner = qkv[(long)s * QKV_O + hh * DD + pd] * scale;
            float r = (d < HALF) ? -partner : partner;
            val = val * cosE[s * ROT + d] + r * sinE[s * ROT + d];
        }
        qout[((size_t)hh * SS + s) * DD + d] = val;
    } else if (c < QP + KP) {
        int kc = c - QP;
        int kv = kc / DD, d = kc % DD;
        float val = v * scale;
        if (d < ROT) {
            int pd = (d < HALF) ? d + HALF : d - HALF;
            float partner = qkv[(long)s * QKV_O + QP + kv * DD + pd] * scale;
            float r = (d < HALF) ? -partner : partner;
            val = val * cosE[s * ROT + d] + r * sinE[s * ROT + d];
        }
        keys[((size_t)kv * DD + d) * SS + s] = val;
    } else {
        int vc = c - QP - KP;
        int kv = vc / DD, d = vc % DD;
        vals[((size_t)kv * SS + s) * DD + d] = v;
    }
}

// ---------------- softmax with causal additive mask -128*mask_flag ----------
__global__ void softmax_kernel(float* __restrict__ sc, const int* __restrict__ maskf)
{
    __shared__ float red[256];
    int s = blockIdx.x, h = blockIdx.y;
    float* row = sc + ((size_t)h * SS + s) * SS;
    int mflag = maskf ? *maskf : 1;
    float mf = -128.f * (float)mflag;
    int tid = threadIdx.x;
    float vals[4];
    float lmax = -3.4e38f;
#pragma unroll
    for (int i = 0; i < 4; i++) {
        int t = tid + i * 256;
        float x = row[t] + ((t <= s) ? 0.f : mf);
        vals[i] = x;
        lmax = fmaxf(lmax, x);
    }
    red[tid] = lmax; __syncthreads();
    for (int st = 128; st > 0; st >>= 1) {
        if (tid < st) red[tid] = fmaxf(red[tid], red[tid + st]);
        __syncthreads();
    }
    float mx = red[0]; __syncthreads();
    float lsum = 0.f;
#pragma unroll
    for (int i = 0; i < 4; i++) { vals[i] = expf(vals[i] - mx); lsum += vals[i]; }
    red[tid] = lsum; __syncthreads();
    for (int st = 128; st > 0; st >>= 1) {
        if (tid < st) red[tid] += red[tid + st];
        __syncthreads();
    }
    float inv = 1.f / red[0];
#pragma unroll
    for (int i = 0; i < 4; i++) row[tid + i * 256] = vals[i] * inv;
}

// ---------------- SiLU(gate)*up ----------------
__global__ void silu_kernel(const float* __restrict__ gu, float* __restrict__ act)
{
    long i = (long)blockIdx.x * blockDim.x + threadIdx.x;
    if (i >= (long)SS * FF) return;
    long s = i / FF, f = i % FF;
    float g = gu[s * 2 * FF + f];
    float u = gu[s * 2 * FF + FF + f];
    act[i] = (g / (1.f + expf(-g))) * u;
}

// ---------------- lm_head: one warp per vocab row ----------------
__global__ void lmhead_kernel(const float* __restrict__ hl,
                              const float* __restrict__ w,
                              float* __restrict__ logits)
{
    int gtid = blockIdx.x * blockDim.x + threadIdx.x;
    int warp = gtid >> 5, lane = gtid & 31;
    if (warp >= VV) return;
    const float* wr = w + (size_t)warp * HID;
    float s = 0.f;
    for (int k = lane; k < HID; k += 32) s = fmaf(hl[k], wr[k], s);
#pragma unroll
    for (int off = 16; off > 0; off >>= 1)
        s += __shfl_down_sync(0xffffffffu, s, off);
    if (lane == 0) logits[warp] = s;
}

// ---------------- argmax + scalar outputs (floats; harness compares f32) ----
__global__ void argmax_kernel(const float* __restrict__ lg, float* __restrict__ outf)
{
    __shared__ float bv[1024];
    __shared__ int   bi[1024];
    int tid = threadIdx.x;
    float best = -3.4e38f; int bidx = 0;
    for (int t = tid; t < VV; t += 1024) {
        float v = lg[t];
        if (v > best) { best = v; bidx = t; }
    }
    bv[tid] = best; bi[tid] = bidx; __syncthreads();
    for (int st = 512; st > 0; st >>= 1) {
        if (tid < st) {
            if (bv[tid + st] > bv[tid] ||
                (bv[tid + st] == bv[tid] && bi[tid + st] < bi[tid])) {
                bv[tid] = bv[tid + st]; bi[tid] = bi[tid + st];
            }
        }
        __syncthreads();
    }
    if (tid == 0) {
        outf[OUT_KVLEN] = (float)SS;
        outf[OUT_TOKEN] = (float)bi[0];
    }
}

// ---------------- launch ----------------
extern "C" void kernel_launch(void* const* d_in, const int* in_sizes, int n_in,
                              void* d_out, int out_size)
{
    // ---- robust binding: identify inputs by element count ----
    int i_ids = -1, i_mask = -1, i_eq = -1, i_lm = -1, i_esc = -1, i_ez = -1;
    int i_l1 = -1, i_l2 = -1, i_qkv = -1, i_ow = -1, i_gu = -1, i_dw = -1;
    int i_nw = -1, i_cos = -1, i_sin = -1;
    for (int i = 0; i < n_in; i++) {
        switch (in_sizes[i]) {
            case 1024:      i_ids = i; break;
            case 1:         i_mask = i; break;
            case 98304000:  if (i_eq < 0) i_eq = i; else i_lm = i; break;
            case 32000:     if (i_esc < 0) i_esc = i; else i_ez = i; break;
            case 6144:      if (i_l1 < 0) i_l1 = i; else i_l2 = i; break;
            case 31457280:  i_qkv = i; break;
            case 18874368:  i_ow = i; break;
            case 100663296: i_gu = i; break;
            case 50331648:  i_dw = i; break;
            case 3072:      i_nw = i; break;
            case 98304:     if (i_cos < 0) i_cos = i; else i_sin = i; break;
            default: break;
        }
    }
    const int*   ids    = (const int*)d_in[i_ids];
    const int*   maskf  = (i_mask >= 0) ? (const int*)d_in[i_mask] : nullptr;
    const void*  eq     = d_in[i_eq];
    const float* escale = (const float*)d_in[i_esc];
    const float* ezero  = (const float*)d_in[i_ez];
    const float* ln1    = (const float*)d_in[i_l1];
    const float* qkvw   = (const float*)d_in[i_qkv];
    const float* ow     = (const float*)d_in[i_ow];
    const float* ln2    = (const float*)d_in[i_l2];
    const float* guw    = (const float*)d_in[i_gu];
    const float* dw     = (const float*)d_in[i_dw];
    const float* normw  = (const float*)d_in[i_nw];
    const float* lmw    = (const float*)d_in[i_lm];
    const float* cosE   = (const float*)d_in[i_cos];
    const float* sinE   = (const float*)d_in[i_sin];
    float* out = (float*)d_out;

    float* scr = nullptr;
    cudaGetSymbolAddress((void**)&scr, g_scratch);
    float* hbuf   = scr + OFF_H;
    float* hn     = scr + OFF_HN;
    float* qkv    = scr + OFF_QKV;
    float* qb     = scr + OFF_Q;
    float* scores = scr + OFF_SC;
    float* ao     = scr + OFF_AO;
    float* gu     = scr + OFF_GU;
    float* act    = scr + OFF_ACT;
    float* hl     = scr + OFF_HL;
    float* logits = scr + OFF_LG;
    int*   flag   = (int*)(scr + OFF_FLAG);
    float* keys   = out + OUT_KEYS;
    float* valsb  = out + OUT_VALS;

    detect_dtype_kernel<<<1, 1>>>((const unsigned int*)eq, flag);
    embed_kernel<<<SS, 256>>>(ids, eq, escale, ezero, flag, hbuf);

    for (int l = 0; l < LL; l++) {
        float* lkeys = keys  + (size_t)l * KVH * DD * SS;
        float* lvals = valsb + (size_t)l * KVH * SS * DD;

        // hn = rms(h, ln1)
        rmsnorm_kernel<<<SS, 256>>>(hbuf, ln1 + (size_t)l * HID, hn, HID);
        // qkv = hn @ qkv_w^T   (N=5120, K=3072)
        tgemm_kernel<true, false><<<dim3(QKV_O / 128, SS / 128, 1), 256>>>(
            hn, HID, 0, qkvw + (size_t)l * QKV_O * HID, HID, 0, 1,
            qkv, QKV_O, 0, HID);
        // split + rope + scale; write K/V caches into d_out
        rope_split_kernel<<<(SS * QKV_O) / 256, 256>>>(qkv, cosE, sinE, qb, lkeys, lvals);
        // scores[h] = q[h] @ k[h/G]   (M=S, N=S, K=D), batched over 24 heads
        tgemm_kernel<false, false><<<dim3(SS / 128, SS / 128, HH), 256>>>(
            qb, DD, (long)SS * DD, lkeys, SS, (long)DD * SS, GG,
            scores, SS, (long)SS * SS, DD);
        // softmax with causal -128*mask
        softmax_kernel<<<dim3(SS, HH), 256>>>(scores, maskf);
        // ao[s, h*D+d] = P[h] @ v[h/G]   (M=S, N=D, K=S)
        tgemm_kernel<false, false><<<dim3(DD / 128, SS / 128, HH), 256>>>(
            scores, SS, (long)SS * SS, lvals, DD, (long)SS * DD, GG,
            ao, HID, (long)DD, SS);
        // h += ao @ o_w^T   (N=3072, K=3072), accumulate
        tgemm_kernel<true, true><<<dim3(HID / 128, SS / 128, 1), 256>>>(
            ao, HID, 0, ow + (size_t)l * HID * QP, QP, 0, 1,
            hbuf, HID, 0, QP);
        // hn = rms(h, ln2)
        rmsnorm_kernel<<<SS, 256>>>(hbuf, ln2 + (size_t)l * HID, hn, HID);
        // gu = hn @ gate_up_w^T  (N=16384, K=3072)
        tgemm_kernel<true, false><<<dim3(2 * FF / 128, SS / 128, 1), 256>>>(
            hn, HID, 0, guw + (size_t)l * 2 * FF * HID, HID, 0, 1,
            gu, 2 * FF, 0, HID);
        // act = silu(gate)*up
        silu_kernel<<<(SS * FF) / 256, 256>>>(gu, act);
        // h += act @ down_w^T   (N=3072, K=8192), accumulate
        tgemm_kernel<true, true><<<dim3(HID / 128, SS / 128, 1), 256>>>(
            act, FF, 0, dw + (size_t)l * HID * FF, FF, 0, 1,
            hbuf, HID, 0, FF);
    }

    // final: rms of last token, lm_head, argmax
    rmsnorm_kernel<<<1, 256>>>(hbuf + (size_t)(SS - 1) * HID, normw, hl, HID);
    lmhead_kernel<<<(VV * 32) / 256, 256>>>(hl, lmw, logits);
    argmax_kernel<<<1, 1024>>>(logits, (float*)d_out);
}

// round 7
// speedup vs baseline: 3.6199x; 1.1034x over previous
#include <cuda_runtime.h>
#include <cuda_bf16.h>
#include <cstdint>
#include <cmath>

// ---------------- problem constants ----------------
#define LL 2
#define HH 24
#define KVH 8
#define GG 3
#define DD 128
#define ROT 96
#define HALF 48
#define HID 3072
#define FF 8192
#define VV 32000
#define SS 1024
#define QP (HH*DD)          // 3072
#define KP (KVH*DD)         // 1024
#define QKV_O (QP + 2*KP)   // 5120
#define EPS 1e-6f
__device__ __constant__ float SCALE_C = 0.29730177875068026f;

// permuted column within 16-block: p = (c&~15) | ((c&3)<<2) | ((c>>2)&3)
#define PERMC(c) (((c) & ~15) | (((c) & 3) << 2) | (((c) >> 2) & 3))

// ---------------- scratch ----------------
#define OFF_H      0ull
#define OFF_HN     (OFF_H   + (size_t)SS*HID)
#define OFF_QKV    (OFF_HN  + (size_t)SS*HID)
#define OFF_Q      (OFF_QKV + (size_t)SS*QKV_O)
#define OFF_SC     (OFF_Q   + (size_t)HH*SS*DD)
#define OFF_AO     (OFF_SC  + (size_t)HH*SS*SS)
#define OFF_GU     (OFF_AO  + (size_t)SS*HID)
#define OFF_ACT    (OFF_GU  + (size_t)SS*2*FF)
#define OFF_HL     (OFF_ACT + (size_t)SS*FF)
#define OFF_LG     (OFF_HL  + (size_t)HID)
#define OFF_FLAG   (OFF_LG  + (size_t)VV)
#define OFF_WQKV   (OFF_FLAG + 16)
#define OFF_WO     (OFF_WQKV + (size_t)LL*QKV_O*HID)
#define OFF_WGU    (OFF_WO   + (size_t)LL*HID*QP)
#define OFF_WDW    (OFF_WGU  + (size_t)LL*2*FF*HID)
#define SCRATCH_TOTAL (OFF_WDW + (size_t)LL*HID*FF)

__device__ float g_scratch[SCRATCH_TOTAL];

// output layout (4-byte elements)
#define OUT_KEYS   0ull
#define OUT_VALS   ((size_t)LL*KVH*DD*SS)
#define OUT_KVLEN  (2ull*LL*KVH*DD*SS)
#define OUT_TOKEN  (OUT_KVLEN + 1)

// ---------------- tf32 / cp.async helpers ----------------
__device__ __forceinline__ unsigned cvt_tf32(float x) {
    unsigned r;
    asm("cvt.rna.tf32.f32 %0, %1;" : "=r"(r) : "f"(x));
    return r;
}
__device__ __forceinline__ void mma_tf32(float* d, const unsigned* a, const unsigned* b) {
    asm("mma.sync.aligned.m16n8k8.row.col.f32.tf32.tf32.f32 "
        "{%0,%1,%2,%3}, {%4,%5,%6,%7}, {%8,%9}, {%0,%1,%2,%3};"
        : "+f"(d[0]), "+f"(d[1]), "+f"(d[2]), "+f"(d[3])
        : "r"(a[0]), "r"(a[1]), "r"(a[2]), "r"(a[3]),
          "r"(b[0]), "r"(b[1]));
}
__device__ __forceinline__ void cp_async16(void* dst, const void* src) {
    unsigned d = (unsigned)__cvta_generic_to_shared(dst);
    asm volatile("cp.async.cg.shared.global [%0], [%1], 16;\n" :: "r"(d), "l"(src));
}
__device__ __forceinline__ void cp_commit() { asm volatile("cp.async.commit_group;\n"); }
__device__ __forceinline__ void cp_wait1()  { asm volatile("cp.async.wait_group 1;\n"); }
__device__ __forceinline__ void cp_wait0()  { asm volatile("cp.async.wait_group 0;\n"); }

// ---------------- dtype probe for embed_q ----------------
__global__ void detect_dtype_kernel(const unsigned int* __restrict__ w,
                                    int* __restrict__ mode)
{
    bool all_small = true, all_f32 = true, all_bf16 = true;
    for (int i = 0; i < 64; i++) {
        unsigned int x = w[i];
        if (x > 255u) all_small = false;
        float f = __uint_as_float(x);
        if (!(f >= 0.f && f <= 255.f && f == rintf(f))) all_f32 = false;
        float f0 = __uint_as_float(x << 16);
        float f1 = __uint_as_float(x & 0xFFFF0000u);
        if (!(f0 >= 0.f && f0 <= 255.f && f0 == rintf(f0) &&
              f1 >= 0.f && f1 <= 255.f && f1 == rintf(f1))) all_bf16 = false;
    }
    *mode = all_small ? 1 : (all_f32 ? 2 : (all_bf16 ? 3 : 0));
}

// ---------------- embed ----------------
__global__ void embed_kernel(const int* __restrict__ ids,
                             const void* __restrict__ eq,
                             const float* __restrict__ escale,
                             const float* __restrict__ ezero,
                             const int* __restrict__ modep,
                             float* __restrict__ h)
{
    int s = blockIdx.x;
    int id = ids[s];
    float sc = escale[id], z = ezero[id];
    float* out = h + (size_t)s * HID;
    int mode = *modep;
    if (mode == 1) {
        const int* row = (const int*)eq + (size_t)id * HID;
        for (int j = threadIdx.x; j < HID; j += blockDim.x)
            out[j] = (float)row[j] * sc + z;
    } else if (mode == 2) {
        const float* row = (const float*)eq + (size_t)id * HID;
        for (int j = threadIdx.x; j < HID; j += blockDim.x)
            out[j] = row[j] * sc + z;
    } else if (mode == 3) {
        const unsigned short* row = (const unsigned short*)eq + (size_t)id * HID;
        for (int j = threadIdx.x; j < HID; j += blockDim.x)
            out[j] = __uint_as_float(((unsigned int)row[j]) << 16) * sc + z;
    } else {
        const unsigned char* row = (const unsigned char*)eq + (size_t)id * HID;
        for (int j = threadIdx.x; j < HID; j += blockDim.x)
            out[j] = (float)row[j] * sc + z;
    }
}

// ---------------- weight convert: fp32 -> tf32(u32), k-permuted ------------
__global__ void convperm_kernel(const float* __restrict__ src,
                                unsigned* __restrict__ dst, long n)
{
    long i4 = ((long)blockIdx.x * blockDim.x + threadIdx.x) * 4;
    if (i4 >= n) return;
    float4 v = *(const float4*)(src + i4);
    long base = i4 & ~15L;
    int j = (int)((i4 >> 2) & 3);
    dst[base + 0 + j] = cvt_tf32(v.x);
    dst[base + 4 + j] = cvt_tf32(v.y);
    dst[base + 8 + j] = cvt_tf32(v.z);
    dst[base + 12 + j] = cvt_tf32(v.w);
}

// ---------------- RMSNorm (optionally tf32-permuted output) ----------------
template<bool TF32P>
__global__ void rmsnorm_kernel(const float* __restrict__ in,
                               const float* __restrict__ w,
                               void* __restrict__ outv, int n)
{
    __shared__ float red[256];
    int row = blockIdx.x;
    const float* x = in + (size_t)row * n;
    float s = 0.f;
    for (int i = threadIdx.x; i < n; i += 256) { float v = x[i]; s += v * v; }
    red[threadIdx.x] = s; __syncthreads();
    for (int st = 128; st > 0; st >>= 1) {
        if (threadIdx.x < st) red[threadIdx.x] += red[threadIdx.x + st];
        __syncthreads();
    }
    float inv = rsqrtf(red[0] / (float)n + EPS);
    if (TF32P) {
        unsigned* y = (unsigned*)outv + (size_t)row * n;
        for (int i = threadIdx.x; i < n; i += 256)
            y[PERMC(i)] = cvt_tf32(w[i] * x[i] * inv);
    } else {
        float* y = (float*)outv + (size_t)row * n;
        for (int i = threadIdx.x; i < n; i += 256)
            y[i] = w[i] * x[i] * inv;
    }
}

// ---------------- old-style GEMM (attention path) ----------------
// OUTMODE: 0 = store f32, 2 = store tf32-permuted u32
#define APAD 20
#define BPAD 136
template<int OUTMODE>
__global__ __launch_bounds__(256, 2) void tgemm_kernel(
    const float* __restrict__ A, int lda, long sA,
    const float* __restrict__ B, int ldb, long sB, int gdivB,
    void* __restrict__ Cv, int ldc, long sC,
    int K)
{
    constexpr int ASZ = 128 * APAD;
    constexpr int BSZ = 16 * BPAD;
    __shared__ __align__(16) float smem[2 * (ASZ + BSZ)];

    int bz = blockIdx.z;
    A += (long)bz * sA;
    B += (long)(bz / gdivB) * sB;
    int m0 = blockIdx.y * 128, n0 = blockIdx.x * 128;
    int tid = threadIdx.x;
    int wid = tid >> 5, lane = tid & 31;
    int wm = (wid >> 2) * 64;
    int wn = (wid & 3) * 32;
    int g = lane >> 2, tig = lane & 3;

    float acc[4][4][4];
#pragma unroll
    for (int mi = 0; mi < 4; mi++)
#pragma unroll
        for (int ni = 0; ni < 4; ni++)
#pragma unroll
            for (int r = 0; r < 4; r++) acc[mi][ni][r] = 0.f;

    int nk = K >> 4;
    int c0 = tid, c1 = tid + 256;

#define PREFETCH_O(s, k0)                                                       \
    {                                                                           \
        float* as = smem + (s) * (ASZ + BSZ);                                   \
        float* bs = as + ASZ;                                                   \
        int r = c0 >> 2, cf = (c0 & 3) * 4;                                     \
        cp_async16(as + r * APAD + cf, A + (long)(m0 + r) * lda + (k0) + cf);   \
        r = c1 >> 2; cf = (c1 & 3) * 4;                                         \
        cp_async16(as + r * APAD + cf, A + (long)(m0 + r) * lda + (k0) + cf);   \
        r = c0 >> 5; cf = (c0 & 31) * 4;                                        \
        cp_async16(bs + r * BPAD + cf, B + (long)((k0) + r) * ldb + n0 + cf);   \
        r = c1 >> 5; cf = (c1 & 31) * 4;                                        \
        cp_async16(bs + r * BPAD + cf, B + (long)((k0) + r) * ldb + n0 + cf);   \
        cp_commit();                                                            \
    }

    PREFETCH_O(0, 0);

    for (int it = 0; it < nk; it++) {
        if (it + 1 < nk) { PREFETCH_O((it + 1) & 1, (it + 1) << 4); cp_wait1(); }
        else             { cp_wait0(); }
        __syncthreads();

        const float* as = smem + (it & 1) * (ASZ + BSZ);
        const float* bs = as + ASZ;

#pragma unroll
        for (int kk = 0; kk < 16; kk += 8) {
            unsigned afr[4][4];
            unsigned bfr[4][2];
#pragma unroll
            for (int mi = 0; mi < 4; mi++) {
                int mr = wm + mi * 16 + g;
                afr[mi][0] = cvt_tf32(as[mr * APAD + kk + tig]);
                afr[mi][1] = cvt_tf32(as[(mr + 8) * APAD + kk + tig]);
                afr[mi][2] = cvt_tf32(as[mr * APAD + kk + tig + 4]);
                afr[mi][3] = cvt_tf32(as[(mr + 8) * APAD + kk + tig + 4]);
            }
#pragma unroll
            for (int ni = 0; ni < 4; ni++) {
                int nc = wn + ni * 8 + g;
                bfr[ni][0] = cvt_tf32(bs[(kk + tig) * BPAD + nc]);
                bfr[ni][1] = cvt_tf32(bs[(kk + tig + 4) * BPAD + nc]);
            }
#pragma unroll
            for (int mi = 0; mi < 4; mi++)
#pragma unroll
                for (int ni = 0; ni < 4; ni++)
                    mma_tf32(acc[mi][ni], afr[mi], bfr[ni]);
        }
        __syncthreads();
    }

#pragma unroll
    for (int mi = 0; mi < 4; mi++) {
        int row = m0 + wm + mi * 16 + g;
#pragma unroll
        for (int ni = 0; ni < 4; ni++) {
            int col = n0 + wn + ni * 8 + 2 * tig;
            if (OUTMODE == 2) {
                unsigned* Cu = (unsigned*)Cv + (long)bz * sC;
                Cu[(long)row * ldc + PERMC(col)]     = cvt_tf32(acc[mi][ni][0]);
                Cu[(long)row * ldc + PERMC(col + 1)] = cvt_tf32(acc[mi][ni][1]);
                Cu[(long)(row + 8) * ldc + PERMC(col)]     = cvt_tf32(acc[mi][ni][2]);
                Cu[(long)(row + 8) * ldc + PERMC(col + 1)] = cvt_tf32(acc[mi][ni][3]);
            } else {
                float* C = (float*)Cv + (long)bz * sC;
                *(float2*)(C + (long)row * ldc + col) =
                    make_float2(acc[mi][ni][0], acc[mi][ni][1]);
                *(float2*)(C + (long)(row + 8) * ldc + col) =
                    make_float2(acc[mi][ni][2], acc[mi][ni][3]);
            }
        }
    }
}
#undef PREFETCH_O

// ---------------- pre-converted tf32 GEMM (weight path, TRANSB) ------------
// A [M,K] u32 tf32 k-permuted, B [N,K] u32 tf32 k-permuted.
// OUTMODE: 0 = store f32, 1 = accumulate f32.
template<int OUTMODE>
__global__ __launch_bounds__(256, 2) void tgemmp_kernel(
    const unsigned* __restrict__ A, int lda,
    const unsigned* __restrict__ B, int ldb,
    float* __restrict__ C, int ldc,
    int K)
{
    __shared__ __align__(16) unsigned smem[2 * 4096];   // per stage: A 2048 + B 2048

    int m0 = blockIdx.y * 128, n0 = blockIdx.x * 128;
    int tid = threadIdx.x;
    int wid = tid >> 5, lane = tid & 31;
    int wm = (wid >> 2) * 64;
    int wn = (wid & 3) * 32;
    int g = lane >> 2, tig = lane & 3;

    float acc[4][4][4];
#pragma unroll
    for (int mi = 0; mi < 4; mi++)
#pragma unroll
        for (int ni = 0; ni < 4; ni++)
#pragma unroll
            for (int r = 0; r < 4; r++) acc[mi][ni][r] = 0.f;

    int nk = K >> 4;
    int c0 = tid, c1 = tid + 256;

#define PREFETCH_P(s, k0)                                                       \
    {                                                                           \
        unsigned* as = smem + (s) * 4096;                                       \
        unsigned* bs = as + 2048;                                               \
        int r = c0 >> 2, cf = (c0 & 3) * 4;                                     \
        cp_async16(as + r * 16 + cf, A + (long)(m0 + r) * lda + (k0) + cf);     \
        r = c1 >> 2; cf = (c1 & 3) * 4;                                         \
        cp_async16(as + r * 16 + cf, A + (long)(m0 + r) * lda + (k0) + cf);     \
        r = c0 >> 2; cf = (c0 & 3) * 4;                                         \
        cp_async16(bs + r * 16 + cf, B + (long)(n0 + r) * ldb + (k0) + cf);     \
        r = c1 >> 2; cf = (c1 & 3) * 4;                                         \
        cp_async16(bs + r * 16 + cf, B + (long)(n0 + r) * ldb + (k0) + cf);     \
        cp_commit();                                                            \
    }

    PREFETCH_P(0, 0);

    for (int it = 0; it < nk; it++) {
        if (it + 1 < nk) { PREFETCH_P((it + 1) & 1, (it + 1) << 4); cp_wait1(); }
        else             { cp_wait0(); }
        __syncthreads();

        const unsigned* as = smem + (it & 1) * 4096;
        const unsigned* bs = as + 2048;

        uint4 qb[4];
#pragma unroll
        for (int ni = 0; ni < 4; ni++)
            qb[ni] = *(const uint4*)&bs[(wn + ni * 8 + g) * 16 + tig * 4];

#pragma unroll
        for (int mi = 0; mi < 4; mi++) {
            int mr = wm + mi * 16 + g;
            uint4 qa0 = *(const uint4*)&as[mr * 16 + tig * 4];
            uint4 qa1 = *(const uint4*)&as[(mr + 8) * 16 + tig * 4];
            unsigned a0[4] = {qa0.x, qa1.x, qa0.y, qa1.y};   // kk = 0
            unsigned a1[4] = {qa0.z, qa1.z, qa0.w, qa1.w};   // kk = 8
#pragma unroll
            for (int ni = 0; ni < 4; ni++) {
                unsigned b0[2] = {qb[ni].x, qb[ni].y};
                unsigned b1[2] = {qb[ni].z, qb[ni].w};
                mma_tf32(acc[mi][ni], a0, b0);
                mma_tf32(acc[mi][ni], a1, b1);
            }
        }
        __syncthreads();
    }

#pragma unroll
    for (int mi = 0; mi < 4; mi++) {
        int row = m0 + wm + mi * 16 + g;
#pragma unroll
        for (int ni = 0; ni < 4; ni++) {
            int col = n0 + wn + ni * 8 + 2 * tig;
            float2* p0 = (float2*)(C + (long)row * ldc + col);
            float2* p1 = (float2*)(C + (long)(row + 8) * ldc + col);
            if (OUTMODE == 1) {
                float2 o0 = *p0, o1 = *p1;
                o0.x += acc[mi][ni][0]; o0.y += acc[mi][ni][1];
                o1.x += acc[mi][ni][2]; o1.y += acc[mi][ni][3];
                *p0 = o0; *p1 = o1;
            } else {
                *p0 = make_float2(acc[mi][ni][0], acc[mi][ni][1]);
                *p1 = make_float2(acc[mi][ni][2], acc[mi][ni][3]);
            }
        }
    }
}
#undef PREFETCH_P

// ---------------- split qkv + rope + scale ----------------
__global__ void rope_split_kernel(const float* __restrict__ qkv,
                                  const float* __restrict__ cosE,
                                  const float* __restrict__ sinE,
                                  float* __restrict__ qout,     // [H][S][D]
                                  float* __restrict__ keys,     // [KV][D][S]
                                  float* __restrict__ vals)     // [KV][S][D]
{
    long idx = (long)blockIdx.x * blockDim.x + threadIdx.x;
    if (idx >= (long)SS * QKV_O) return;
    int s = (int)(idx / QKV_O);
    int c = (int)(idx % QKV_O);
    float v = qkv[idx];
    float scale = SCALE_C;
    if (c < QP) {
        int hh = c / DD, d = c % DD;
        float val = v * scale;
        if (d < ROT) {
            int pd = (d < HALF) ? d + HALF : d - HALF;
            float partner = qkv[(long)s * QKV_O + hh * DD + pd] * scale;
            float r = (d < HALF) ? -partner : partner;
            val = val * cosE[s * ROT + d] + r * sinE[s * ROT + d];
        }
        qout[((size_t)hh * SS + s) * DD + d] = val;
    } else if (c < QP + KP) {
        int kc = c - QP;
        int kv = kc / DD, d = kc % DD;
        float val = v * scale;
        if (d < ROT) {
            int pd = (d < HALF) ? d + HALF : d - HALF;
            float partner = qkv[(long)s * QKV_O + QP + kv * DD + pd] * scale;
            float r = (d < HALF) ? -partner : partner;
            val = val * cosE[s * ROT + d] + r * sinE[s * ROT + d];
        }
        keys[((size_t)kv * DD + d) * SS + s] = val;
    } else {
        int vc = c - QP - KP;
        int kv = vc / DD, d = vc % DD;
        vals[((size_t)kv * SS + s) * DD + d] = v;
    }
}

// ---------------- softmax with causal mask ----------------
__global__ void softmax_kernel(float* __restrict__ sc, const int* __restrict__ maskf)
{
    __shared__ float red[256];
    int s = blockIdx.x, h = blockIdx.y;
    float* row = sc + ((size_t)h * SS + s) * SS;
    int mflag = maskf ? *maskf : 1;
    float mf = -128.f * (float)mflag;
    int tid = threadIdx.x;
    float vals[4];
    float lmax = -3.4e38f;
#pragma unroll
    for (int i = 0; i < 4; i++) {
        int t = tid + i * 256;
        float x = row[t] + ((t <= s) ? 0.f : mf);
        vals[i] = x;
        lmax = fmaxf(lmax, x);
    }
    red[tid] = lmax; __syncthreads();
    for (int st = 128; st > 0; st >>= 1) {
        if (tid < st) red[tid] = fmaxf(red[tid], red[tid + st]);
        __syncthreads();
    }
    float mx = red[0]; __syncthreads();
    float lsum = 0.f;
#pragma unroll
    for (int i = 0; i < 4; i++) { vals[i] = expf(vals[i] - mx); lsum += vals[i]; }
    red[tid] = lsum; __syncthreads();
    for (int st = 128; st > 0; st >>= 1) {
        if (tid < st) red[tid] += red[tid + st];
        __syncthreads();
    }
    float inv = 1.f / red[0];
#pragma unroll
    for (int i = 0; i < 4; i++) row[tid + i * 256] = vals[i] * inv;
}

// ---------------- SiLU(gate)*up -> tf32-permuted u32 ----------------
__global__ void silu_kernel(const float* __restrict__ gu, unsigned* __restrict__ act)
{
    long i = (long)blockIdx.x * blockDim.x + threadIdx.x;
    if (i >= (long)SS * FF) return;
    long s = i / FF, f = i % FF;
    float g = gu[s * 2 * FF + f];
    float u = gu[s * 2 * FF + FF + f];
    float v = (g / (1.f + expf(-g))) * u;
    act[(i & ~15L) | (long)(((int)(i & 3)) << 2) | (long)(((int)(i >> 2)) & 3)] = cvt_tf32(v);
}

// ---------------- lm_head ----------------
__global__ void lmhead_kernel(const float* __restrict__ hl,
                              const float* __restrict__ w,
                              float* __restrict__ logits)
{
    int gtid = blockIdx.x * blockDim.x + threadIdx.x;
    int warp = gtid >> 5, lane = gtid & 31;
    if (warp >= VV) return;
    const float* wr = w + (size_t)warp * HID;
    float s = 0.f;
    for (int k = lane; k < HID; k += 32) s = fmaf(hl[k], wr[k], s);
#pragma unroll
    for (int off = 16; off > 0; off >>= 1)
        s += __shfl_down_sync(0xffffffffu, s, off);
    if (lane == 0) logits[warp] = s;
}

// ---------------- argmax + scalar outputs ----------------
__global__ void argmax_kernel(const float* __restrict__ lg, float* __restrict__ outf)
{
    __shared__ float bv[1024];
    __shared__ int   bi[1024];
    int tid = threadIdx.x;
    float best = -3.4e38f; int bidx = 0;
    for (int t = tid; t < VV; t += 1024) {
        float v = lg[t];
        if (v > best) { best = v; bidx = t; }
    }
    bv[tid] = best; bi[tid] = bidx; __syncthreads();
    for (int st = 512; st > 0; st >>= 1) {
        if (tid < st) {
            if (bv[tid + st] > bv[tid] ||
                (bv[tid + st] == bv[tid] && bi[tid + st] < bi[tid])) {
                bv[tid] = bv[tid + st]; bi[tid] = bi[tid + st];
            }
        }
        __syncthreads();
    }
    if (tid == 0) {
        outf[OUT_KVLEN] = (float)SS;
        outf[OUT_TOKEN] = (float)bi[0];
    }
}

// ---------------- launch ----------------
extern "C" void kernel_launch(void* const* d_in, const int* in_sizes, int n_in,
                              void* d_out, int out_size)
{
    int i_ids = -1, i_mask = -1, i_eq = -1, i_lm = -1, i_esc = -1, i_ez = -1;
    int i_l1 = -1, i_l2 = -1, i_qkv = -1, i_ow = -1, i_gu = -1, i_dw = -1;
    int i_nw = -1, i_cos = -1, i_sin = -1;
    for (int i = 0; i < n_in; i++) {
        switch (in_sizes[i]) {
            case 1024:      i_ids = i; break;
            case 1:         i_mask = i; break;
            case 98304000:  if (i_eq < 0) i_eq = i; else i_lm = i; break;
            case 32000:     if (i_esc < 0) i_esc = i; else i_ez = i; break;
            case 6144:      if (i_l1 < 0) i_l1 = i; else i_l2 = i; break;
            case 31457280:  i_qkv = i; break;
            case 18874368:  i_ow = i; break;
            case 100663296: i_gu = i; break;
            case 50331648:  i_dw = i; break;
            case 3072:      i_nw = i; break;
            case 98304:     if (i_cos < 0) i_cos = i; else i_sin = i; break;
            default: break;
        }
    }
    const int*   ids    = (const int*)d_in[i_ids];
    const int*   maskf  = (i_mask >= 0) ? (const int*)d_in[i_mask] : nullptr;
    const void*  eq     = d_in[i_eq];
    const float* escale = (const float*)d_in[i_esc];
    const float* ezero  = (const float*)d_in[i_ez];
    const float* ln1    = (const float*)d_in[i_l1];
    const float* qkvw   = (const float*)d_in[i_qkv];
    const float* ow     = (const float*)d_in[i_ow];
    const float* ln2    = (const float*)d_in[i_l2];
    const float* guw    = (const float*)d_in[i_gu];
    const float* dw     = (const float*)d_in[i_dw];
    const float* normw  = (const float*)d_in[i_nw];
    const float* lmw    = (const float*)d_in[i_lm];
    const float* cosE   = (const float*)d_in[i_cos];
    const float* sinE   = (const float*)d_in[i_sin];
    float* out = (float*)d_out;

    float* scr = nullptr;
    cudaGetSymbolAddress((void**)&scr, g_scratch);
    float*    hbuf   = scr + OFF_H;
    unsigned* hn_u   = (unsigned*)(scr + OFF_HN);
    float*    qkv    = scr + OFF_QKV;
    float*    qb     = scr + OFF_Q;
    float*    scores = scr + OFF_SC;
    unsigned* ao_u   = (unsigned*)(scr + OFF_AO);
    float*    gu     = scr + OFF_GU;
    unsigned* act_u  = (unsigned*)(scr + OFF_ACT);
    float*    hl     = scr + OFF_HL;
    float*    logits = scr + OFF_LG;
    int*      flag   = (int*)(scr + OFF_FLAG);
    unsigned* wqkv_c = (unsigned*)(scr + OFF_WQKV);
    unsigned* wo_c   = (unsigned*)(scr + OFF_WO);
    unsigned* wgu_c  = (unsigned*)(scr + OFF_WGU);
    unsigned* wdw_c  = (unsigned*)(scr + OFF_WDW);
    float*    keys   = out + OUT_KEYS;
    float*    valsb  = out + OUT_VALS;

    // ---- one-time-per-launch weight conversion (tf32 + k-permute) ----
    {
        long n;
        n = (long)LL * QKV_O * HID;
        convperm_kernel<<<(unsigned)((n / 4 + 255) / 256), 256>>>(qkvw, wqkv_c, n);
        n = (long)LL * HID * QP;
        convperm_kernel<<<(unsigned)((n / 4 + 255) / 256), 256>>>(ow, wo_c, n);
        n = (long)LL * 2 * FF * HID;
        convperm_kernel<<<(unsigned)((n / 4 + 255) / 256), 256>>>(guw, wgu_c, n);
        n = (long)LL * HID * FF;
        convperm_kernel<<<(unsigned)((n / 4 + 255) / 256), 256>>>(dw, wdw_c, n);
    }

    detect_dtype_kernel<<<1, 1>>>((const unsigned int*)eq, flag);
    embed_kernel<<<SS, 256>>>(ids, eq, escale, ezero, flag, hbuf);

    for (int l = 0; l < LL; l++) {
        float* lkeys = keys  + (size_t)l * KVH * DD * SS;
        float* lvals = valsb + (size_t)l * KVH * SS * DD;

        // hn = rms(h, ln1)  (tf32-permuted)
        rmsnorm_kernel<true><<<SS, 256>>>(hbuf, ln1 + (size_t)l * HID, hn_u, HID);
        // qkv = hn @ qkv_w^T
        tgemmp_kernel<0><<<dim3(QKV_O / 128, SS / 128, 1), 256>>>(
            hn_u, HID, wqkv_c + (size_t)l * QKV_O * HID, HID,
            qkv, QKV_O, HID);
        // rope + split
        rope_split_kernel<<<(SS * QKV_O) / 256, 256>>>(qkv, cosE, sinE, qb, lkeys, lvals);
        // scores = q @ k (batched over heads)
        tgemm_kernel<0><<<dim3(SS / 128, SS / 128, HH), 256>>>(
            qb, DD, (long)SS * DD, lkeys, SS, (long)DD * SS, GG,
            scores, SS, (long)SS * SS, DD);
        softmax_kernel<<<dim3(SS, HH), 256>>>(scores, maskf);
        // ao = P @ v  -> tf32-permuted u32
        tgemm_kernel<2><<<dim3(DD / 128, SS / 128, HH), 256>>>(
            scores, SS, (long)SS * SS, lvals, DD, (long)SS * DD, GG,
            ao_u, HID, (long)DD, SS);
        // h += ao @ o_w^T
        tgemmp_kernel<1><<<dim3(HID / 128, SS / 128, 1), 256>>>(
            ao_u, QP, wo_c + (size_t)l * HID * QP, QP,
            hbuf, HID, QP);
        // hn = rms(h, ln2) (tf32-permuted)
        rmsnorm_kernel<true><<<SS, 256>>>(hbuf, ln2 + (size_t)l * HID, hn_u, HID);
        // gu = hn @ gate_up_w^T
        tgemmp_kernel<0><<<dim3(2 * FF / 128, SS / 128, 1), 256>>>(
            hn_u, HID, wgu_c + (size_t)l * 2 * FF * HID, HID,
            gu, 2 * FF, HID);
        // act = silu(gate)*up  -> tf32-permuted u32
        silu_kernel<<<(SS * FF) / 256, 256>>>(gu, act_u);
        // h += act @ down_w^T
        tgemmp_kernel<1><<<dim3(HID / 128, SS / 128, 1), 256>>>(
            act_u, FF, wdw_c + (size_t)l * HID * FF, FF,
            hbuf, HID, FF);
    }

    rmsnorm_kernel<false><<<1, 256>>>(hbuf + (size_t)(SS - 1) * HID, normw, hl, HID);
    lmhead_kernel<<<(VV * 32) / 256, 256>>>(hl, lmw, logits);
    argmax_kernel<<<1, 1024>>>(logits, (float*)d_out);
}

// round 8
// speedup vs baseline: 3.7196x; 1.0275x over previous
#include <cuda_runtime.h>
#include <cuda_bf16.h>
#include <cstdint>
#include <cmath>

// ---------------- problem constants ----------------
#define LL 2
#define HH 24
#define KVH 8
#define GG 3
#define DD 128
#define ROT 96
#define HALF 48
#define HID 3072
#define FF 8192
#define VV 32000
#define SS 1024
#define QP (HH*DD)          // 3072
#define KP (KVH*DD)         // 1024
#define QKV_O (QP + 2*KP)   // 5120
#define EPS 1e-6f
__device__ __constant__ float SCALE_C = 0.29730177875068026f;

// permuted column within 16-block: p = (c&~15) | ((c&3)<<2) | ((c>>2)&3)
#define PERMC(c) (((c) & ~15) | (((c) & 3) << 2) | (((c) >> 2) & 3))

// ---------------- scratch ----------------
#define OFF_H      0ull
#define OFF_HN     (OFF_H   + (size_t)SS*HID)
#define OFF_QKV    (OFF_HN  + (size_t)SS*HID)
#define OFF_Q      (OFF_QKV + (size_t)SS*QKV_O)
#define OFF_SC     (OFF_Q   + (size_t)HH*SS*DD)
#define OFF_AO     (OFF_SC  + (size_t)HH*SS*SS)
#define OFF_GU     (OFF_AO  + (size_t)SS*HID)
#define OFF_ACT    (OFF_GU  + (size_t)SS*2*FF)
#define OFF_HL     (OFF_ACT + (size_t)SS*FF)
#define OFF_LG     (OFF_HL  + (size_t)HID)
#define OFF_FLAG   (OFF_LG  + (size_t)VV)
#define OFF_WQKV   (OFF_FLAG + 16)
#define OFF_WO     (OFF_WQKV + (size_t)LL*QKV_O*HID)
#define OFF_WGU    (OFF_WO   + (size_t)LL*HID*QP)
#define OFF_WDW    (OFF_WGU  + (size_t)LL*2*FF*HID)
#define SCRATCH_TOTAL (OFF_WDW + (size_t)LL*HID*FF)

__device__ float g_scratch[SCRATCH_TOTAL];

// output layout (4-byte elements)
#define OUT_KEYS   0ull
#define OUT_VALS   ((size_t)LL*KVH*DD*SS)
#define OUT_KVLEN  (2ull*LL*KVH*DD*SS)
#define OUT_TOKEN  (OUT_KVLEN + 1)

// ---------------- tf32 / cp.async helpers ----------------
__device__ __forceinline__ unsigned cvt_tf32(float x) {
    unsigned r;
    asm("cvt.rna.tf32.f32 %0, %1;" : "=r"(r) : "f"(x));
    return r;
}
__device__ __forceinline__ void mma_tf32(float* d, const unsigned* a, const unsigned* b) {
    asm("mma.sync.aligned.m16n8k8.row.col.f32.tf32.tf32.f32 "
        "{%0,%1,%2,%3}, {%4,%5,%6,%7}, {%8,%9}, {%0,%1,%2,%3};"
        : "+f"(d[0]), "+f"(d[1]), "+f"(d[2]), "+f"(d[3])
        : "r"(a[0]), "r"(a[1]), "r"(a[2]), "r"(a[3]),
          "r"(b[0]), "r"(b[1]));
}
__device__ __forceinline__ void cp_async16(void* dst, const void* src) {
    unsigned d = (unsigned)__cvta_generic_to_shared(dst);
    asm volatile("cp.async.cg.shared.global [%0], [%1], 16;\n" :: "r"(d), "l"(src));
}
__device__ __forceinline__ void cp_commit() { asm volatile("cp.async.commit_group;\n"); }
__device__ __forceinline__ void cp_wait1()  { asm volatile("cp.async.wait_group 1;\n"); }
__device__ __forceinline__ void cp_wait0()  { asm volatile("cp.async.wait_group 0;\n"); }

// ---------------- dtype probe for embed_q ----------------
__global__ void detect_dtype_kernel(const unsigned int* __restrict__ w,
                                    int* __restrict__ mode)
{
    bool all_small = true, all_f32 = true, all_bf16 = true;
    for (int i = 0; i < 64; i++) {
        unsigned int x = w[i];
        if (x > 255u) all_small = false;
        float f = __uint_as_float(x);
        if (!(f >= 0.f && f <= 255.f && f == rintf(f))) all_f32 = false;
        float f0 = __uint_as_float(x << 16);
        float f1 = __uint_as_float(x & 0xFFFF0000u);
        if (!(f0 >= 0.f && f0 <= 255.f && f0 == rintf(f0) &&
              f1 >= 0.f && f1 <= 255.f && f1 == rintf(f1))) all_bf16 = false;
    }
    *mode = all_small ? 1 : (all_f32 ? 2 : (all_bf16 ? 3 : 0));
}

// ---------------- embed ----------------
__global__ void embed_kernel(const int* __restrict__ ids,
                             const void* __restrict__ eq,
                             const float* __restrict__ escale,
                             const float* __restrict__ ezero,
                             const int* __restrict__ modep,
                             float* __restrict__ h)
{
    int s = blockIdx.x;
    int id = ids[s];
    float sc = escale[id], z = ezero[id];
    float* out = h + (size_t)s * HID;
    int mode = *modep;
    if (mode == 1) {
        const int* row = (const int*)eq + (size_t)id * HID;
        for (int j = threadIdx.x; j < HID; j += blockDim.x)
            out[j] = (float)row[j] * sc + z;
    } else if (mode == 2) {
        const float* row = (const float*)eq + (size_t)id * HID;
        for (int j = threadIdx.x; j < HID; j += blockDim.x)
            out[j] = row[j] * sc + z;
    } else if (mode == 3) {
        const unsigned short* row = (const unsigned short*)eq + (size_t)id * HID;
        for (int j = threadIdx.x; j < HID; j += blockDim.x)
            out[j] = __uint_as_float(((unsigned int)row[j]) << 16) * sc + z;
    } else {
        const unsigned char* row = (const unsigned char*)eq + (size_t)id * HID;
        for (int j = threadIdx.x; j < HID; j += blockDim.x)
            out[j] = (float)row[j] * sc + z;
    }
}

// ---------------- weight convert: fp32 -> tf32(u32), k-permuted ------------
__global__ void convperm_kernel(const float* __restrict__ src,
                                unsigned* __restrict__ dst, long n)
{
    long i4 = ((long)blockIdx.x * blockDim.x + threadIdx.x) * 4;
    if (i4 >= n) return;
    float4 v = *(const float4*)(src + i4);
    long base = i4 & ~15L;
    int j = (int)((i4 >> 2) & 3);
    dst[base + 0 + j] = cvt_tf32(v.x);
    dst[base + 4 + j] = cvt_tf32(v.y);
    dst[base + 8 + j] = cvt_tf32(v.z);
    dst[base + 12 + j] = cvt_tf32(v.w);
}

// ---------------- RMSNorm (optionally tf32-permuted output) ----------------
template<bool TF32P>
__global__ void rmsnorm_kernel(const float* __restrict__ in,
                               const float* __restrict__ w,
                               void* __restrict__ outv, int n)
{
    __shared__ float red[256];
    int row = blockIdx.x;
    const float* x = in + (size_t)row * n;
    float s = 0.f;
    for (int i = threadIdx.x; i < n; i += 256) { float v = x[i]; s += v * v; }
    red[threadIdx.x] = s; __syncthreads();
    for (int st = 128; st > 0; st >>= 1) {
        if (threadIdx.x < st) red[threadIdx.x] += red[threadIdx.x + st];
        __syncthreads();
    }
    float inv = rsqrtf(red[0] / (float)n + EPS);
    if (TF32P) {
        unsigned* y = (unsigned*)outv + (size_t)row * n;
        for (int i = threadIdx.x; i < n; i += 256)
            y[PERMC(i)] = cvt_tf32(w[i] * x[i] * inv);
    } else {
        float* y = (float*)outv + (size_t)row * n;
        for (int i = threadIdx.x; i < n; i += 256)
            y[i] = w[i] * x[i] * inv;
    }
}

// ---------------- old-style GEMM (attention path) ----------------
// OUTMODE: 0 = store f32, 2 = store tf32-permuted u32
#define APAD 20
#define BPAD 136
template<int OUTMODE>
__global__ __launch_bounds__(256, 2) void tgemm_kernel(
    const float* __restrict__ A, int lda, long sA,
    const float* __restrict__ B, int ldb, long sB, int gdivB,
    void* __restrict__ Cv, int ldc, long sC,
    int K)
{
    constexpr int ASZ = 128 * APAD;
    constexpr int BSZ = 16 * BPAD;
    __shared__ __align__(16) float smem[2 * (ASZ + BSZ)];

    int bz = blockIdx.z;
    A += (long)bz * sA;
    B += (long)(bz / gdivB) * sB;
    int m0 = blockIdx.y * 128, n0 = blockIdx.x * 128;
    int tid = threadIdx.x;
    int wid = tid >> 5, lane = tid & 31;
    int wm = (wid >> 2) * 64;
    int wn = (wid & 3) * 32;
    int g = lane >> 2, tig = lane & 3;

    float acc[4][4][4];
#pragma unroll
    for (int mi = 0; mi < 4; mi++)
#pragma unroll
        for (int ni = 0; ni < 4; ni++)
#pragma unroll
            for (int r = 0; r < 4; r++) acc[mi][ni][r] = 0.f;

    int nk = K >> 4;
    int c0 = tid, c1 = tid + 256;

#define PREFETCH_O(s, k0)                                                       \
    {                                                                           \
        float* as = smem + (s) * (ASZ + BSZ);                                   \
        float* bs = as + ASZ;                                                   \
        int r = c0 >> 2, cf = (c0 & 3) * 4;                                     \
        cp_async16(as + r * APAD + cf, A + (long)(m0 + r) * lda + (k0) + cf);   \
        r = c1 >> 2; cf = (c1 & 3) * 4;                                         \
        cp_async16(as + r * APAD + cf, A + (long)(m0 + r) * lda + (k0) + cf);   \
        r = c0 >> 5; cf = (c0 & 31) * 4;                                        \
        cp_async16(bs + r * BPAD + cf, B + (long)((k0) + r) * ldb + n0 + cf);   \
        r = c1 >> 5; cf = (c1 & 31) * 4;                                        \
        cp_async16(bs + r * BPAD + cf, B + (long)((k0) + r) * ldb + n0 + cf);   \
        cp_commit();                                                            \
    }

    PREFETCH_O(0, 0);

    for (int it = 0; it < nk; it++) {
        if (it + 1 < nk) { PREFETCH_O((it + 1) & 1, (it + 1) << 4); cp_wait1(); }
        else             { cp_wait0(); }
        __syncthreads();

        const float* as = smem + (it & 1) * (ASZ + BSZ);
        const float* bs = as + ASZ;

#pragma unroll
        for (int kk = 0; kk < 16; kk += 8) {
            unsigned afr[4][4];
            unsigned bfr[4][2];
#pragma unroll
            for (int mi = 0; mi < 4; mi++) {
                int mr = wm + mi * 16 + g;
                afr[mi][0] = cvt_tf32(as[mr * APAD + kk + tig]);
                afr[mi][1] = cvt_tf32(as[(mr + 8) * APAD + kk + tig]);
                afr[mi][2] = cvt_tf32(as[mr * APAD + kk + tig + 4]);
                afr[mi][3] = cvt_tf32(as[(mr + 8) * APAD + kk + tig + 4]);
            }
#pragma unroll
            for (int ni = 0; ni < 4; ni++) {
                int nc = wn + ni * 8 + g;
                bfr[ni][0] = cvt_tf32(bs[(kk + tig) * BPAD + nc]);
                bfr[ni][1] = cvt_tf32(bs[(kk + tig + 4) * BPAD + nc]);
            }
#pragma unroll
            for (int mi = 0; mi < 4; mi++)
#pragma unroll
                for (int ni = 0; ni < 4; ni++)
                    mma_tf32(acc[mi][ni], afr[mi], bfr[ni]);
        }
        __syncthreads();
    }

#pragma unroll
    for (int mi = 0; mi < 4; mi++) {
        int row = m0 + wm + mi * 16 + g;
#pragma unroll
        for (int ni = 0; ni < 4; ni++) {
            int col = n0 + wn + ni * 8 + 2 * tig;
            if (OUTMODE == 2) {
                unsigned* Cu = (unsigned*)Cv + (long)bz * sC;
                Cu[(long)row * ldc + PERMC(col)]     = cvt_tf32(acc[mi][ni][0]);
                Cu[(long)row * ldc + PERMC(col + 1)] = cvt_tf32(acc[mi][ni][1]);
                Cu[(long)(row + 8) * ldc + PERMC(col)]     = cvt_tf32(acc[mi][ni][2]);
                Cu[(long)(row + 8) * ldc + PERMC(col + 1)] = cvt_tf32(acc[mi][ni][3]);
            } else {
                float* C = (float*)Cv + (long)bz * sC;
                *(float2*)(C + (long)row * ldc + col) =
                    make_float2(acc[mi][ni][0], acc[mi][ni][1]);
                *(float2*)(C + (long)(row + 8) * ldc + col) =
                    make_float2(acc[mi][ni][2], acc[mi][ni][3]);
            }
        }
    }
}
#undef PREFETCH_O

// ---------------- pre-converted tf32 GEMM (weight path, TRANSB) ------------
// A [M,K] u32 tf32 k-permuted, B [N,K] u32 tf32 k-permuted.
// CTA 128x128, 4 warps (128 thr), warp tile 64x64 (2x2 warp grid).
// OUTMODE: 0 = store f32, 1 = accumulate f32.
template<int OUTMODE>
__global__ __launch_bounds__(128, 2) void tgemmp_kernel(
    const unsigned* __restrict__ A, int lda,
    const unsigned* __restrict__ B, int ldb,
    float* __restrict__ C, int ldc,
    int K)
{
    __shared__ __align__(16) unsigned smem[2 * 4096];   // per stage: A 2048 + B 2048

    int m0 = blockIdx.y * 128, n0 = blockIdx.x * 128;
    int tid = threadIdx.x;
    int wid = tid >> 5, lane = tid & 31;
    int wm = (wid >> 1) * 64;          // 2 warps in m
    int wn = (wid & 1) * 64;           // 2 warps in n
    int g = lane >> 2, tig = lane & 3;

    float acc[4][8][4];
#pragma unroll
    for (int mi = 0; mi < 4; mi++)
#pragma unroll
        for (int ni = 0; ni < 8; ni++)
#pragma unroll
            for (int r = 0; r < 4; r++) acc[mi][ni][r] = 0.f;

    int nk = K >> 4;

#define PREFETCH_P(s, k0)                                                       \
    {                                                                           \
        unsigned* as = smem + (s) * 4096;                                       \
        unsigned* bs = as + 2048;                                               \
        _Pragma("unroll")                                                       \
        for (int i = 0; i < 4; i++) {                                           \
            int c = tid + i * 128;                                              \
            int r = c >> 2, cf = (c & 3) * 4;                                   \
            cp_async16(as + r * 16 + cf, A + (long)(m0 + r) * lda + (k0) + cf); \
            cp_async16(bs + r * 16 + cf, B + (long)(n0 + r) * ldb + (k0) + cf); \
        }                                                                       \
        cp_commit();                                                            \
    }

    PREFETCH_P(0, 0);

    for (int it = 0; it < nk; it++) {
        if (it + 1 < nk) { PREFETCH_P((it + 1) & 1, (it + 1) << 4); cp_wait1(); }
        else             { cp_wait0(); }
        __syncthreads();

        const unsigned* as = smem + (it & 1) * 4096;
        const unsigned* bs = as + 2048;

        uint4 qb[8];
#pragma unroll
        for (int ni = 0; ni < 8; ni++)
            qb[ni] = *(const uint4*)&bs[(wn + ni * 8 + g) * 16 + tig * 4];

#pragma unroll
        for (int mi = 0; mi < 4; mi++) {
            int mr = wm + mi * 16 + g;
            uint4 qa0 = *(const uint4*)&as[mr * 16 + tig * 4];
            uint4 qa1 = *(const uint4*)&as[(mr + 8) * 16 + tig * 4];
            unsigned a0[4] = {qa0.x, qa1.x, qa0.y, qa1.y};   // kk = 0
            unsigned a1[4] = {qa0.z, qa1.z, qa0.w, qa1.w};   // kk = 8
#pragma unroll
            for (int ni = 0; ni < 8; ni++) {
                unsigned b0[2] = {qb[ni].x, qb[ni].y};
                unsigned b1[2] = {qb[ni].z, qb[ni].w};
                mma_tf32(acc[mi][ni], a0, b0);
                mma_tf32(acc[mi][ni], a1, b1);
            }
        }
        __syncthreads();
    }

#pragma unroll
    for (int mi = 0; mi < 4; mi++) {
        int row = m0 + wm + mi * 16 + g;
#pragma unroll
        for (int ni = 0; ni < 8; ni++) {
            int col = n0 + wn + ni * 8 + 2 * tig;
            float2* p0 = (float2*)(C + (long)row * ldc + col);
            float2* p1 = (float2*)(C + (long)(row + 8) * ldc + col);
            if (OUTMODE == 1) {
                float2 o0 = *p0, o1 = *p1;
                o0.x += acc[mi][ni][0]; o0.y += acc[mi][ni][1];
                o1.x += acc[mi][ni][2]; o1.y += acc[mi][ni][3];
                *p0 = o0; *p1 = o1;
            } else {
                *p0 = make_float2(acc[mi][ni][0], acc[mi][ni][1]);
                *p1 = make_float2(acc[mi][ni][2], acc[mi][ni][3]);
            }
        }
    }
}
#undef PREFETCH_P

// ---------------- split qkv + rope + scale ----------------
__global__ void rope_split_kernel(const float* __restrict__ qkv,
                                  const float* __restrict__ cosE,
                                  const float* __restrict__ sinE,
                                  float* __restrict__ qout,     // [H][S][D]
                                  float* __restrict__ keys,     // [KV][D][S]
                                  float* __restrict__ vals)     // [KV][S][D]
{
    long idx = (long)blockIdx.x * blockDim.x + threadIdx.x;
    if (idx >= (long)SS * QKV_O) return;
    int s = (int)(idx / QKV_O);
    int c = (int)(idx % QKV_O);
    float v = qkv[idx];
    float scale = SCALE_C;
    if (c < QP) {
        int hh = c / DD, d = c % DD;
        float val = v * scale;
        if (d < ROT) {
            int pd = (d < HALF) ? d + HALF : d - HALF;
            float partner = qkv[(long)s * QKV_O + hh * DD + pd] * scale;
            float r = (d < HALF) ? -partner : partner;
            val = val * cosE[s * ROT + d] + r * sinE[s * ROT + d];
        }
        qout[((size_t)hh * SS + s) * DD + d] = val;
    } else if (c < QP + KP) {
        int kc = c - QP;
        int kv = kc / DD, d = kc % DD;
        float val = v * scale;
        if (d < ROT) {
            int pd = (d < HALF) ? d + HALF : d - HALF;
            float partner = qkv[(long)s * QKV_O + QP + kv * DD + pd] * scale;
            float r = (d < HALF) ? -partner : partner;
            val = val * cosE[s * ROT + d] + r * sinE[s * ROT + d];
        }
        keys[((size_t)kv * DD + d) * SS + s] = val;
    } else {
        int vc = c - QP - KP;
        int kv = vc / DD, d = vc % DD;
        vals[((size_t)kv * SS + s) * DD + d] = v;
    }
}

// ---------------- softmax with causal mask ----------------
__global__ void softmax_kernel(float* __restrict__ sc, const int* __restrict__ maskf)
{
    __shared__ float red[256];
    int s = blockIdx.x, h = blockIdx.y;
    float* row = sc + ((size_t)h * SS + s) * SS;
    int mflag = maskf ? *maskf : 1;
    float mf = -128.f * (float)mflag;
    int tid = threadIdx.x;
    float vals[4];
    float lmax = -3.4e38f;
#pragma unroll
    for (int i = 0; i < 4; i++) {
        int t = tid + i * 256;
        float x = row[t] + ((t <= s) ? 0.f : mf);
        vals[i] = x;
        lmax = fmaxf(lmax, x);
    }
    red[tid] = lmax; __syncthreads();
    for (int st = 128; st > 0; st >>= 1) {
        if (tid < st) red[tid] = fmaxf(red[tid], red[tid + st]);
        __syncthreads();
    }
    float mx = red[0]; __syncthreads();
    float lsum = 0.f;
#pragma unroll
    for (int i = 0; i < 4; i++) { vals[i] = expf(vals[i] - mx); lsum += vals[i]; }
    red[tid] = lsum; __syncthreads();
    for (int st = 128; st > 0; st >>= 1) {
        if (tid < st) red[tid] += red[tid + st];
        __syncthreads();
    }
    float inv = 1.f / red[0];
#pragma unroll
    for (int i = 0; i < 4; i++) row[tid + i * 256] = vals[i] * inv;
}

// ---------------- SiLU(gate)*up -> tf32-permuted u32 ----------------
__global__ void silu_kernel(const float* __restrict__ gu, unsigned* __restrict__ act)
{
    long i = (long)blockIdx.x * blockDim.x + threadIdx.x;
    if (i >= (long)SS * FF) return;
    long s = i / FF, f = i % FF;
    float g = gu[s * 2 * FF + f];
    float u = gu[s * 2 * FF + FF + f];
    float v = (g / (1.f + expf(-g))) * u;
    act[(i & ~15L) | (long)(((int)(i & 3)) << 2) | (long)(((int)(i >> 2)) & 3)] = cvt_tf32(v);
}

// ---------------- lm_head ----------------
__global__ void lmhead_kernel(const float* __restrict__ hl,
                              const float* __restrict__ w,
                              float* __restrict__ logits)
{
    int gtid = blockIdx.x * blockDim.x + threadIdx.x;
    int warp = gtid >> 5, lane = gtid & 31;
    if (warp >= VV) return;
    const float* wr = w + (size_t)warp * HID;
    float s = 0.f;
    for (int k = lane; k < HID; k += 32) s = fmaf(hl[k], wr[k], s);
#pragma unroll
    for (int off = 16; off > 0; off >>= 1)
        s += __shfl_down_sync(0xffffffffu, s, off);
    if (lane == 0) logits[warp] = s;
}

// ---------------- argmax + scalar outputs ----------------
__global__ void argmax_kernel(const float* __restrict__ lg, float* __restrict__ outf)
{
    __shared__ float bv[1024];
    __shared__ int   bi[1024];
    int tid = threadIdx.x;
    float best = -3.4e38f; int bidx = 0;
    for (int t = tid; t < VV; t += 1024) {
        float v = lg[t];
        if (v > best) { best = v; bidx = t; }
    }
    bv[tid] = best; bi[tid] = bidx; __syncthreads();
    for (int st = 512; st > 0; st >>= 1) {
        if (tid < st) {
            if (bv[tid + st] > bv[tid] ||
                (bv[tid + st] == bv[tid] && bi[tid + st] < bi[tid])) {
                bv[tid] = bv[tid + st]; bi[tid] = bi[tid + st];
            }
        }
        __syncthreads();
    }
    if (tid == 0) {
        outf[OUT_KVLEN] = (float)SS;
        outf[OUT_TOKEN] = (float)bi[0];
    }
}

// ---------------- launch ----------------
extern "C" void kernel_launch(void* const* d_in, const int* in_sizes, int n_in,
                              void* d_out, int out_size)
{
    int i_ids = -1, i_mask = -1, i_eq = -1, i_lm = -1, i_esc = -1, i_ez = -1;
    int i_l1 = -1, i_l2 = -1, i_qkv = -1, i_ow = -1, i_gu = -1, i_dw = -1;
    int i_nw = -1, i_cos = -1, i_sin = -1;
    for (int i = 0; i < n_in; i++) {
        switch (in_sizes[i]) {
            case 1024:      i_ids = i; break;
            case 1:         i_mask = i; break;
            case 98304000:  if (i_eq < 0) i_eq = i; else i_lm = i; break;
            case 32000:     if (i_esc < 0) i_esc = i; else i_ez = i; break;
            case 6144:      if (i_l1 < 0) i_l1 = i; else i_l2 = i; break;
            case 31457280:  i_qkv = i; break;
            case 18874368:  i_ow = i; break;
            case 100663296: i_gu = i; break;
            case 50331648:  i_dw = i; break;
            case 3072:      i_nw = i; break;
            case 98304:     if (i_cos < 0) i_cos = i; else i_sin = i; break;
            default: break;
        }
    }
    const int*   ids    = (const int*)d_in[i_ids];
    const int*   maskf  = (i_mask >= 0) ? (const int*)d_in[i_mask] : nullptr;
    const void*  eq     = d_in[i_eq];
    const float* escale = (const float*)d_in[i_esc];
    const float* ezero  = (const float*)d_in[i_ez];
    const float* ln1    = (const float*)d_in[i_l1];
    const float* qkvw   = (const float*)d_in[i_qkv];
    const float* ow     = (const float*)d_in[i_ow];
    const float* ln2    = (const float*)d_in[i_l2];
    const float* guw    = (const float*)d_in[i_gu];
    const float* dw     = (const float*)d_in[i_dw];
    const float* normw  = (const float*)d_in[i_nw];
    const float* lmw    = (const float*)d_in[i_lm];
    const float* cosE   = (const float*)d_in[i_cos];
    const float* sinE   = (const float*)d_in[i_sin];
    float* out = (float*)d_out;

    float* scr = nullptr;
    cudaGetSymbolAddress((void**)&scr, g_scratch);
    float*    hbuf   = scr + OFF_H;
    unsigned* hn_u   = (unsigned*)(scr + OFF_HN);
    float*    qkv    = scr + OFF_QKV;
    float*    qb     = scr + OFF_Q;
    float*    scores = scr + OFF_SC;
    unsigned* ao_u   = (unsigned*)(scr + OFF_AO);
    float*    gu     = scr + OFF_GU;
    unsigned* act_u  = (unsigned*)(scr + OFF_ACT);
    float*    hl     = scr + OFF_HL;
    float*    logits = scr + OFF_LG;
    int*      flag   = (int*)(scr + OFF_FLAG);
    unsigned* wqkv_c = (unsigned*)(scr + OFF_WQKV);
    unsigned* wo_c   = (unsigned*)(scr + OFF_WO);
    unsigned* wgu_c  = (unsigned*)(scr + OFF_WGU);
    unsigned* wdw_c  = (unsigned*)(scr + OFF_WDW);
    float*    keys   = out + OUT_KEYS;
    float*    valsb  = out + OUT_VALS;

    // ---- one-time-per-launch weight conversion (tf32 + k-permute) ----
    {
        long n;
        n = (long)LL * QKV_O * HID;
        convperm_kernel<<<(unsigned)((n / 4 + 255) / 256), 256>>>(qkvw, wqkv_c, n);
        n = (long)LL * HID * QP;
        convperm_kernel<<<(unsigned)((n / 4 + 255) / 256), 256>>>(ow, wo_c, n);
        n = (long)LL * 2 * FF * HID;
        convperm_kernel<<<(unsigned)((n / 4 + 255) / 256), 256>>>(guw, wgu_c, n);
        n = (long)LL * HID * FF;
        convperm_kernel<<<(unsigned)((n / 4 + 255) / 256), 256>>>(dw, wdw_c, n);
    }

    detect_dtype_kernel<<<1, 1>>>((const unsigned int*)eq, flag);
    embed_kernel<<<SS, 256>>>(ids, eq, escale, ezero, flag, hbuf);

    for (int l = 0; l < LL; l++) {
        float* lkeys = keys  + (size_t)l * KVH * DD * SS;
        float* lvals = valsb + (size_t)l * KVH * SS * DD;

        // hn = rms(h, ln1)  (tf32-permuted)
        rmsnorm_kernel<true><<<SS, 256>>>(hbuf, ln1 + (size_t)l * HID, hn_u, HID);
        // qkv = hn @ qkv_w^T
        tgemmp_kernel<0><<<dim3(QKV_O / 128, SS / 128, 1), 128>>>(
            hn_u, HID, wqkv_c + (size_t)l * QKV_O * HID, HID,
            qkv, QKV_O, HID);
        // rope + split
        rope_split_kernel<<<(SS * QKV_O) / 256, 256>>>(qkv, cosE, sinE, qb, lkeys, lvals);
        // scores = q @ k (batched over heads)
        tgemm_kernel<0><<<dim3(SS / 128, SS / 128, HH), 256>>>(
            qb, DD, (long)SS * DD, lkeys, SS, (long)DD * SS, GG,
            scores, SS, (long)SS * SS, DD);
        softmax_kernel<<<dim3(SS, HH), 256>>>(scores, maskf);
        // ao = P @ v  -> tf32-permuted u32
        tgemm_kernel<2><<<dim3(DD / 128, SS / 128, HH), 256>>>(
            scores, SS, (long)SS * SS, lvals, DD, (long)SS * DD, GG,
            ao_u, HID, (long)DD, SS);
        // h += ao @ o_w^T
        tgemmp_kernel<1><<<dim3(HID / 128, SS / 128, 1), 128>>>(
            ao_u, QP, wo_c + (size_t)l * HID * QP, QP,
            hbuf, HID, QP);
        // hn = rms(h, ln2) (tf32-permuted)
        rmsnorm_kernel<true><<<SS, 256>>>(hbuf, ln2 + (size_t)l * HID, hn_u, HID);
        // gu = hn @ gate_up_w^T
        tgemmp_kernel<0><<<dim3(2 * FF / 128, SS / 128, 1), 128>>>(
            hn_u, HID, wgu_c + (size_t)l * 2 * FF * HID, HID,
            gu, 2 * FF, HID);
        // act = silu(gate)*up  -> tf32-permuted u32
        silu_kernel<<<(SS * FF) / 256, 256>>>(gu, act_u);
        // h += act @ down_w^T
        tgemmp_kernel<1><<<dim3(HID / 128, SS / 128, 1), 128>>>(
            act_u, FF, wdw_c + (size_t)l * HID * FF, FF,
            hbuf, HID, FF);
    }

    rmsnorm_kernel<false><<<1, 256>>>(hbuf + (size_t)(SS - 1) * HID, normw, hl, HID);
    lmhead_kernel<<<(VV * 32) / 256, 256>>>(hl, lmw, logits);
    argmax_kernel<<<1, 1024>>>(logits, (float*)d_out);
}

// round 10
// speedup vs baseline: 3.7316x; 1.0032x over previous
#include <cuda_runtime.h>
#include <cuda_bf16.h>
#include <cstdint>
#include <cmath>

// ---------------- problem constants ----------------
#define LL 2
#define HH 24
#define KVH 8
#define GG 3
#define DD 128
#define ROT 96
#define HALF 48
#define HID 3072
#define FF 8192
#define VV 32000
#define SS 1024
#define QP (HH*DD)          // 3072
#define KP (KVH*DD)         // 1024
#define QKV_O (QP + 2*KP)   // 5120
#define EPS 1e-6f
__device__ __constant__ float SCALE_C = 0.29730177875068026f;

// permuted column within 16-block: p = (c&~15) | ((c&3)<<2) | ((c>>2)&3)
#define PERMC(c) (((c) & ~15) | (((c) & 3) << 2) | (((c) >> 2) & 3))

// ---------------- scratch ----------------
#define OFF_H      0ull
#define OFF_HN     (OFF_H   + (size_t)SS*HID)
#define OFF_QKV    (OFF_HN  + (size_t)SS*HID)
#define OFF_Q      (OFF_QKV + (size_t)SS*QKV_O)
#define OFF_SC     (OFF_Q   + (size_t)HH*SS*DD)
#define OFF_AO     (OFF_SC  + (size_t)HH*SS*SS)
#define OFF_GU     (OFF_AO  + (size_t)SS*HID)
#define OFF_ACT    (OFF_GU  + (size_t)SS*2*FF)
#define OFF_HL     (OFF_ACT + (size_t)SS*FF)
#define OFF_LG     (OFF_HL  + (size_t)HID)
#define OFF_FLAG   (OFF_LG  + (size_t)VV)
#define OFF_WQKV   (OFF_FLAG + 16)
#define OFF_WO     (OFF_WQKV + (size_t)LL*QKV_O*HID)
#define OFF_WGU    (OFF_WO   + (size_t)LL*HID*QP)
#define OFF_WDW    (OFF_WGU  + (size_t)LL*2*FF*HID)
#define SCRATCH_TOTAL (OFF_WDW + (size_t)LL*HID*FF)

__device__ float g_scratch[SCRATCH_TOTAL];

// output layout (4-byte elements)
#define OUT_KEYS   0ull
#define OUT_VALS   ((size_t)LL*KVH*DD*SS)
#define OUT_KVLEN  (2ull*LL*KVH*DD*SS)
#define OUT_TOKEN  (OUT_KVLEN + 1)

// ---------------- tf32 / cp.async helpers ----------------
__device__ __forceinline__ unsigned cvt_tf32(float x) {
    unsigned r;
    asm("cvt.rna.tf32.f32 %0, %1;" : "=r"(r) : "f"(x));
    return r;
}
__device__ __forceinline__ void mma_tf32(float* d, const unsigned* a, const unsigned* b) {
    asm("mma.sync.aligned.m16n8k8.row.col.f32.tf32.tf32.f32 "
        "{%0,%1,%2,%3}, {%4,%5,%6,%7}, {%8,%9}, {%0,%1,%2,%3};"
        : "+f"(d[0]), "+f"(d[1]), "+f"(d[2]), "+f"(d[3])
        : "r"(a[0]), "r"(a[1]), "r"(a[2]), "r"(a[3]),
          "r"(b[0]), "r"(b[1]));
}
__device__ __forceinline__ void cp_async16(void* dst, const void* src) {
    unsigned d = (unsigned)__cvta_generic_to_shared(dst);
    asm volatile("cp.async.cg.shared.global [%0], [%1], 16;\n" :: "r"(d), "l"(src));
}
__device__ __forceinline__ void cp_commit() { asm volatile("cp.async.commit_group;\n"); }
__device__ __forceinline__ void cp_wait1()  { asm volatile("cp.async.wait_group 1;\n"); }
__device__ __forceinline__ void cp_wait0()  { asm volatile("cp.async.wait_group 0;\n"); }

// ---------------- dtype probe for embed_q ----------------
__global__ void detect_dtype_kernel(const unsigned int* __restrict__ w,
                                    int* __restrict__ mode)
{
    bool all_small = true, all_f32 = true, all_bf16 = true;
    for (int i = 0; i < 64; i++) {
        unsigned int x = w[i];
        if (x > 255u) all_small = false;
        float f = __uint_as_float(x);
        if (!(f >= 0.f && f <= 255.f && f == rintf(f))) all_f32 = false;
        float f0 = __uint_as_float(x << 16);
        float f1 = __uint_as_float(x & 0xFFFF0000u);
        if (!(f0 >= 0.f && f0 <= 255.f && f0 == rintf(f0) &&
              f1 >= 0.f && f1 <= 255.f && f1 == rintf(f1))) all_bf16 = false;
    }
    *mode = all_small ? 1 : (all_f32 ? 2 : (all_bf16 ? 3 : 0));
}

// ---------------- embed ----------------
__global__ void embed_kernel(const int* __restrict__ ids,
                             const void* __restrict__ eq,
                             const float* __restrict__ escale,
                             const float* __restrict__ ezero,
                             const int* __restrict__ modep,
                             float* __restrict__ h)
{
    int s = blockIdx.x;
    int id = ids[s];
    float sc = escale[id], z = ezero[id];
    float* out = h + (size_t)s * HID;
    int mode = *modep;
    if (mode == 1) {
        const int* row = (const int*)eq + (size_t)id * HID;
        for (int j = threadIdx.x; j < HID; j += blockDim.x)
            out[j] = (float)row[j] * sc + z;
    } else if (mode == 2) {
        const float* row = (const float*)eq + (size_t)id * HID;
        for (int j = threadIdx.x; j < HID; j += blockDim.x)
            out[j] = row[j] * sc + z;
    } else if (mode == 3) {
        const unsigned short* row = (const unsigned short*)eq + (size_t)id * HID;
        for (int j = threadIdx.x; j < HID; j += blockDim.x)
            out[j] = __uint_as_float(((unsigned int)row[j]) << 16) * sc + z;
    } else {
        const unsigned char* row = (const unsigned char*)eq + (size_t)id * HID;
        for (int j = threadIdx.x; j < HID; j += blockDim.x)
            out[j] = (float)row[j] * sc + z;
    }
}

// ---------------- weight convert: fp32 -> tf32(u32), k-permuted ------------
__global__ void convperm_kernel(const float* __restrict__ src,
                                unsigned* __restrict__ dst, long n)
{
    long i4 = ((long)blockIdx.x * blockDim.x + threadIdx.x) * 4;
    if (i4 >= n) return;
    float4 v = *(const float4*)(src + i4);
    long base = i4 & ~15L;
    int j = (int)((i4 >> 2) & 3);
    dst[base + 0 + j] = cvt_tf32(v.x);
    dst[base + 4 + j] = cvt_tf32(v.y);
    dst[base + 8 + j] = cvt_tf32(v.z);
    dst[base + 12 + j] = cvt_tf32(v.w);
}

// ---------------- RMSNorm (optionally tf32-permuted output) ----------------
template<bool TF32P>
__global__ void rmsnorm_kernel(const float* __restrict__ in,
                               const float* __restrict__ w,
                               void* __restrict__ outv, int n)
{
    __shared__ float red[256];
    int row = blockIdx.x;
    const float* x = in + (size_t)row * n;
    float s = 0.f;
    for (int i = threadIdx.x; i < n; i += 256) { float v = x[i]; s += v * v; }
    red[threadIdx.x] = s; __syncthreads();
    for (int st = 128; st > 0; st >>= 1) {
        if (threadIdx.x < st) red[threadIdx.x] += red[threadIdx.x + st];
        __syncthreads();
    }
    float inv = rsqrtf(red[0] / (float)n + EPS);
    if (TF32P) {
        unsigned* y = (unsigned*)outv + (size_t)row * n;
        for (int i = threadIdx.x; i < n; i += 256)
            y[PERMC(i)] = cvt_tf32(w[i] * x[i] * inv);
    } else {
        float* y = (float*)outv + (size_t)row * n;
        for (int i = threadIdx.x; i < n; i += 256)
            y[i] = w[i] * x[i] * inv;
    }
}

// ---------------- mma.sync GEMM (attention path), 3-stage pipeline ---------
// OUTMODE: 0 = store f32, 2 = store tf32-permuted u32
#define APAD 20
#define BPAD 136
template<int OUTMODE>
__global__ __launch_bounds__(256, 2) void tgemm_kernel(
    const float* __restrict__ A, int lda, long sA,
    const float* __restrict__ B, int ldb, long sB, int gdivB,
    void* __restrict__ Cv, int ldc, long sC,
    int K)
{
    constexpr int ASZ = 128 * APAD;
    constexpr int BSZ = 16 * BPAD;
    constexpr int STG = ASZ + BSZ;
    __shared__ __align__(16) float smem[3 * STG];

    int bz = blockIdx.z;
    A += (long)bz * sA;
    B += (long)(bz / gdivB) * sB;
    int m0 = blockIdx.y * 128, n0 = blockIdx.x * 128;
    int tid = threadIdx.x;
    int wid = tid >> 5, lane = tid & 31;
    int wm = (wid >> 2) * 64;
    int wn = (wid & 3) * 32;
    int g = lane >> 2, tig = lane & 3;

    float acc[4][4][4];
#pragma unroll
    for (int mi = 0; mi < 4; mi++)
#pragma unroll
        for (int ni = 0; ni < 4; ni++)
#pragma unroll
            for (int r = 0; r < 4; r++) acc[mi][ni][r] = 0.f;

    int nk = K >> 4;
    int c0 = tid, c1 = tid + 256;

#define PREFETCH_O(s, k0)                                                       \
    {                                                                           \
        float* as = smem + (s) * STG;                                           \
        float* bs = as + ASZ;                                                   \
        int r = c0 >> 2, cf = (c0 & 3) * 4;                                     \
        cp_async16(as + r * APAD + cf, A + (long)(m0 + r) * lda + (k0) + cf);   \
        r = c1 >> 2; cf = (c1 & 3) * 4;                                         \
        cp_async16(as + r * APAD + cf, A + (long)(m0 + r) * lda + (k0) + cf);   \
        r = c0 >> 5; cf = (c0 & 31) * 4;                                        \
        cp_async16(bs + r * BPAD + cf, B + (long)((k0) + r) * ldb + n0 + cf);   \
        r = c1 >> 5; cf = (c1 & 31) * 4;                                        \
        cp_async16(bs + r * BPAD + cf, B + (long)((k0) + r) * ldb + n0 + cf);   \
        cp_commit();                                                            \
    }

    PREFETCH_O(0, 0);
    if (nk > 1) PREFETCH_O(1, 16);

    int bufc = 0, bufp = 2;
    for (int it = 0; it < nk; it++) {
        if (it + 1 < nk) cp_wait1(); else cp_wait0();
        __syncthreads();
        if (it + 2 < nk) {
            PREFETCH_O(bufp, (it + 2) << 4);
            bufp = (bufp == 2) ? 0 : bufp + 1;
        }

        const float* as = smem + bufc * STG;
        const float* bs = as + ASZ;
        bufc = (bufc == 2) ? 0 : bufc + 1;

#pragma unroll
        for (int kk = 0; kk < 16; kk += 8) {
            unsigned afr[4][4];
            unsigned bfr[4][2];
#pragma unroll
            for (int mi = 0; mi < 4; mi++) {
                int mr = wm + mi * 16 + g;
                afr[mi][0] = cvt_tf32(as[mr * APAD + kk + tig]);
                afr[mi][1] = cvt_tf32(as[(mr + 8) * APAD + kk + tig]);
                afr[mi][2] = cvt_tf32(as[mr * APAD + kk + tig + 4]);
                afr[mi][3] = cvt_tf32(as[(mr + 8) * APAD + kk + tig + 4]);
            }
#pragma unroll
            for (int ni = 0; ni < 4; ni++) {
                int nc = wn + ni * 8 + g;
                bfr[ni][0] = cvt_tf32(bs[(kk + tig) * BPAD + nc]);
                bfr[ni][1] = cvt_tf32(bs[(kk + tig + 4) * BPAD + nc]);
            }
#pragma unroll
            for (int mi = 0; mi < 4; mi++)
#pragma unroll
                for (int ni = 0; ni < 4; ni++)
                    mma_tf32(acc[mi][ni], afr[mi], bfr[ni]);
        }
    }

#pragma unroll
    for (int mi = 0; mi < 4; mi++) {
        int row = m0 + wm + mi * 16 + g;
#pragma unroll
        for (int ni = 0; ni < 4; ni++) {
            int col = n0 + wn + ni * 8 + 2 * tig;
            if (OUTMODE == 2) {
                unsigned* Cu = (unsigned*)Cv + (long)bz * sC;
                Cu[(long)row * ldc + PERMC(col)]     = cvt_tf32(acc[mi][ni][0]);
                Cu[(long)row * ldc + PERMC(col + 1)] = cvt_tf32(acc[mi][ni][1]);
                Cu[(long)(row + 8) * ldc + PERMC(col)]     = cvt_tf32(acc[mi][ni][2]);
                Cu[(long)(row + 8) * ldc + PERMC(col + 1)] = cvt_tf32(acc[mi][ni][3]);
            } else {
                float* C = (float*)Cv + (long)bz * sC;
                *(float2*)(C + (long)row * ldc + col) =
                    make_float2(acc[mi][ni][0], acc[mi][ni][1]);
                *(float2*)(C + (long)(row + 8) * ldc + col) =
                    make_float2(acc[mi][ni][2], acc[mi][ni][3]);
            }
        }
    }
}
#undef PREFETCH_O

// ---------------- pre-converted tf32 GEMM (weight path), 3-stage ------------
// A [M,K] u32 tf32 k-permuted, B [N,K] u32 tf32 k-permuted.
// CTA 128x128, 4 warps (128 thr), warp tile 64x64 (2x2 warp grid).
// OUTMODE: 0 = store f32, 1 = accumulate f32.
template<int OUTMODE>
__global__ __launch_bounds__(128, 2) void tgemmp_kernel(
    const unsigned* __restrict__ A, int lda,
    const unsigned* __restrict__ B, int ldb,
    float* __restrict__ C, int ldc,
    int K)
{
    __shared__ __align__(16) unsigned smem[3 * 4096];   // per stage: A 2048 + B 2048

    int m0 = blockIdx.y * 128, n0 = blockIdx.x * 128;
    int tid = threadIdx.x;
    int wid = tid >> 5, lane = tid & 31;
    int wm = (wid >> 1) * 64;          // 2 warps in m
    int wn = (wid & 1) * 64;           // 2 warps in n
    int g = lane >> 2, tig = lane & 3;

    float acc[4][8][4];
#pragma unroll
    for (int mi = 0; mi < 4; mi++)
#pragma unroll
        for (int ni = 0; ni < 8; ni++)
#pragma unroll
            for (int r = 0; r < 4; r++) acc[mi][ni][r] = 0.f;

    int nk = K >> 4;

#define PREFETCH_P(s, k0)                                                       \
    {                                                                           \
        unsigned* as = smem + (s) * 4096;                                       \
        unsigned* bs = as + 2048;                                               \
        _Pragma("unroll")                                                       \
        for (int i = 0; i < 4; i++) {                                           \
            int c = tid + i * 128;                                              \
            int r = c >> 2, cf = (c & 3) * 4;                                   \
            cp_async16(as + r * 16 + cf, A + (long)(m0 + r) * lda + (k0) + cf); \
            cp_async16(bs + r * 16 + cf, B + (long)(n0 + r) * ldb + (k0) + cf); \
        }                                                                       \
        cp_commit();                                                            \
    }

    PREFETCH_P(0, 0);
    if (nk > 1) PREFETCH_P(1, 16);

    int bufc = 0, bufp = 2;
    for (int it = 0; it < nk; it++) {
        if (it + 1 < nk) cp_wait1(); else cp_wait0();
        __syncthreads();
        if (it + 2 < nk) {
            PREFETCH_P(bufp, (it + 2) << 4);
            bufp = (bufp == 2) ? 0 : bufp + 1;
        }

        const unsigned* as = smem + bufc * 4096;
        const unsigned* bs = as + 2048;
        bufc = (bufc == 2) ? 0 : bufc + 1;

        uint4 qb[8];
#pragma unroll
        for (int ni = 0; ni < 8; ni++)
            qb[ni] = *(const uint4*)&bs[(wn + ni * 8 + g) * 16 + tig * 4];

#pragma unroll
        for (int mi = 0; mi < 4; mi++) {
            int mr = wm + mi * 16 + g;
            uint4 qa0 = *(const uint4*)&as[mr * 16 + tig * 4];
            uint4 qa1 = *(const uint4*)&as[(mr + 8) * 16 + tig * 4];
            unsigned a0[4] = {qa0.x, qa1.x, qa0.y, qa1.y};   // kk = 0
            unsigned a1[4] = {qa0.z, qa1.z, qa0.w, qa1.w};   // kk = 8
#pragma unroll
            for (int ni = 0; ni < 8; ni++) {
                unsigned b0[2] = {qb[ni].x, qb[ni].y};
                unsigned b1[2] = {qb[ni].z, qb[ni].w};
                mma_tf32(acc[mi][ni], a0, b0);
                mma_tf32(acc[mi][ni], a1, b1);
            }
        }
    }

#pragma unroll
    for (int mi = 0; mi < 4; mi++) {
        int row = m0 + wm + mi * 16 + g;
#pragma unroll
        for (int ni = 0; ni < 8; ni++) {
            int col = n0 + wn + ni * 8 + 2 * tig;
            float2* p0 = (float2*)(C + (long)row * ldc + col);
            float2* p1 = (float2*)(C + (long)(row + 8) * ldc + col);
            if (OUTMODE == 1) {
                float2 o0 = *p0, o1 = *p1;
                o0.x += acc[mi][ni][0]; o0.y += acc[mi][ni][1];
                o1.x += acc[mi][ni][2]; o1.y += acc[mi][ni][3];
                *p0 = o0; *p1 = o1;
            } else {
                *p0 = make_float2(acc[mi][ni][0], acc[mi][ni][1]);
                *p1 = make_float2(acc[mi][ni][2], acc[mi][ni][3]);
            }
        }
    }
}
#undef PREFETCH_P

// ---------------- split qkv + rope + scale ----------------
__global__ void rope_split_kernel(const float* __restrict__ qkv,
                                  const float* __restrict__ cosE,
                                  const float* __restrict__ sinE,
                                  float* __restrict__ qout,     // [H][S][D]
                                  float* __restrict__ keys,     // [KV][D][S]
                                  float* __restrict__ vals)     // [KV][S][D]
{
    long idx = (long)blockIdx.x * blockDim.x + threadIdx.x;
    if (idx >= (long)SS * QKV_O) return;
    int s = (int)(idx / QKV_O);
    int c = (int)(idx % QKV_O);
    float v = qkv[idx];
    float scale = SCALE_C;
    if (c < QP) {
        int hh = c / DD, d = c % DD;
        float val = v * scale;
        if (d < ROT) {
            int pd = (d < HALF) ? d + HALF : d - HALF;
            float partner = qkv[(long)s * QKV_O + hh * DD + pd] * scale;
            float r = (d < HALF) ? -partner : partner;
            val = val * cosE[s * ROT + d] + r * sinE[s * ROT + d];
        }
        qout[((size_t)hh * SS + s) * DD + d] = val;
    } else if (c < QP + KP) {
        int kc = c - QP;
        int kv = kc / DD, d = kc % DD;
        float val = v * scale;
        if (d < ROT) {
            int pd = (d < HALF) ? d + HALF : d - HALF;
            float partner = qkv[(long)s * QKV_O + QP + kv * DD + pd] * scale;
            float r = (d < HALF) ? -partner : partner;
            val = val * cosE[s * ROT + d] + r * sinE[s * ROT + d];
        }
        keys[((size_t)kv * DD + d) * SS + s] = val;
    } else {
        int vc = c - QP - KP;
        int kv = vc / DD, d = vc % DD;
        vals[((size_t)kv * SS + s) * DD + d] = v;
    }
}

// ---------------- softmax with causal mask ----------------
__global__ void softmax_kernel(float* __restrict__ sc, const int* __restrict__ maskf)
{
    __shared__ float red[256];
    int s = blockIdx.x, h = blockIdx.y;
    float* row = sc + ((size_t)h * SS + s) * SS;
    int mflag = maskf ? *maskf : 1;
    float mf = -128.f * (float)mflag;
    int tid = threadIdx.x;
    float vals[4];
    float lmax = -3.4e38f;
#pragma unroll
    for (int i = 0; i < 4; i++) {
        int t = tid + i * 256;
        float x = row[t] + ((t <= s) ? 0.f : mf);
        vals[i] = x;
        lmax = fmaxf(lmax, x);
    }
    red[tid] = lmax; __syncthreads();
    for (int st = 128; st > 0; st >>= 1) {
        if (tid < st) red[tid] = fmaxf(red[tid], red[tid + st]);
        __syncthreads();
    }
    float mx = red[0]; __syncthreads();
    float lsum = 0.f;
#pragma unroll
    for (int i = 0; i < 4; i++) { vals[i] = expf(vals[i] - mx); lsum += vals[i]; }
    red[tid] = lsum; __syncthreads();
    for (int st = 128; st > 0; st >>= 1) {
        if (tid < st) red[tid] += red[tid + st];
        __syncthreads();
    }
    float inv = 1.f / red[0];
#pragma unroll
    for (int i = 0; i < 4; i++) row[tid + i * 256] = vals[i] * inv;
}

// ---------------- SiLU(gate)*up -> tf32-permuted u32 ----------------
__global__ void silu_kernel(const float* __restrict__ gu, unsigned* __restrict__ act)
{
    long i = (long)blockIdx.x * blockDim.x + threadIdx.x;
    if (i >= (long)SS * FF) return;
    long s = i / FF, f = i % FF;
    float g = gu[s * 2 * FF + f];
    float u = gu[s * 2 * FF + FF + f];
    float v = (g / (1.f + expf(-g))) * u;
    act[(i & ~15L) | (long)(((int)(i & 3)) << 2) | (long)(((int)(i >> 2)) & 3)] = cvt_tf32(v);
}

// ---------------- lm_head ----------------
__global__ void lmhead_kernel(const float* __restrict__ hl,
                              const float* __restrict__ w,
                              float* __restrict__ logits)
{
    int gtid = blockIdx.x * blockDim.x + threadIdx.x;
    int warp = gtid >> 5, lane = gtid & 31;
    if (warp >= VV) return;
    const float* wr = w + (size_t)warp * HID;
    float s = 0.f;
    for (int k = lane; k < HID; k += 32) s = fmaf(hl[k], wr[k], s);
#pragma unroll
    for (int off = 16; off > 0; off >>= 1)
        s += __shfl_down_sync(0xffffffffu, s, off);
    if (lane == 0) logits[warp] = s;
}

// ---------------- argmax + scalar outputs ----------------
__global__ void argmax_kernel(const float* __restrict__ lg, float* __restrict__ outf)
{
    __shared__ float bv[1024];
    __shared__ int   bi[1024];
    int tid = threadIdx.x;
    float best = -3.4e38f; int bidx = 0;
    for (int t = tid; t < VV; t += 1024) {
        float v = lg[t];
        if (v > best) { best = v; bidx = t; }
    }
    bv[tid] = best; bi[tid] = bidx; __syncthreads();
    for (int st = 512; st > 0; st >>= 1) {
        if (tid < st) {
            if (bv[tid + st] > bv[tid] ||
                (bv[tid + st] == bv[tid] && bi[tid + st] < bi[tid])) {
                bv[tid] = bv[tid + st]; bi[tid] = bi[tid + st];
            }
        }
        __syncthreads();
    }
    if (tid == 0) {
        outf[OUT_KVLEN] = (float)SS;
        outf[OUT_TOKEN] = (float)bi[0];
    }
}

// ---------------- launch ----------------
extern "C" void kernel_launch(void* const* d_in, const int* in_sizes, int n_in,
                              void* d_out, int out_size)
{
    int i_ids = -1, i_mask = -1, i_eq = -1, i_lm = -1, i_esc = -1, i_ez = -1;
    int i_l1 = -1, i_l2 = -1, i_qkv = -1, i_ow = -1, i_gu = -1, i_dw = -1;
    int i_nw = -1, i_cos = -1, i_sin = -1;
    for (int i = 0; i < n_in; i++) {
        switch (in_sizes[i]) {
            case 1024:      i_ids = i; break;
            case 1:         i_mask = i; break;
            case 98304000:  if (i_eq < 0) i_eq = i; else i_lm = i; break;
            case 32000:     if (i_esc < 0) i_esc = i; else i_ez = i; break;
            case 6144:      if (i_l1 < 0) i_l1 = i; else i_l2 = i; break;
            case 31457280:  i_qkv = i; break;
            case 18874368:  i_ow = i; break;
            case 100663296: i_gu = i; break;
            case 50331648:  i_dw = i; break;
            case 3072:      i_nw = i; break;
            case 98304:     if (i_cos < 0) i_cos = i; else i_sin = i; break;
            default: break;
        }
    }
    const int*   ids    = (const int*)d_in[i_ids];
    const int*   maskf  = (i_mask >= 0) ? (const int*)d_in[i_mask] : nullptr;
    const void*  eq     = d_in[i_eq];
    const float* escale = (const float*)d_in[i_esc];
    const float* ezero  = (const float*)d_in[i_ez];
    const float* ln1    = (const float*)d_in[i_l1];
    const float* qkvw   = (const float*)d_in[i_qkv];
    const float* ow     = (const float*)d_in[i_ow];
    const float* ln2    = (const float*)d_in[i_l2];
    const float* guw    = (const float*)d_in[i_gu];
    const float* dw     = (const float*)d_in[i_dw];
    const float* normw  = (const float*)d_in[i_nw];
    const float* lmw    = (const float*)d_in[i_lm];
    const float* cosE   = (const float*)d_in[i_cos];
    const float* sinE   = (const float*)d_in[i_sin];
    float* out = (float*)d_out;

    float* scr = nullptr;
    cudaGetSymbolAddress((void**)&scr, g_scratch);
    float*    hbuf   = scr + OFF_H;
    unsigned* hn_u   = (unsigned*)(scr + OFF_HN);
    float*    qkv    = scr + OFF_QKV;
    float*    qb     = scr + OFF_Q;
    float*    scores = scr + OFF_SC;
    unsigned* ao_u   = (unsigned*)(scr + OFF_AO);
    float*    gu     = scr + OFF_GU;
    unsigned* act_u  = (unsigned*)(scr + OFF_ACT);
    float*    hl     = scr + OFF_HL;
    float*    logits = scr + OFF_LG;
    int*      flag   = (int*)(scr + OFF_FLAG);
    unsigned* wqkv_c = (unsigned*)(scr + OFF_WQKV);
    unsigned* wo_c   = (unsigned*)(scr + OFF_WO);
    unsigned* wgu_c  = (unsigned*)(scr + OFF_WGU);
    unsigned* wdw_c  = (unsigned*)(scr + OFF_WDW);
    float*    keys   = out + OUT_KEYS;
    float*    valsb  = out + OUT_VALS;

    // ---- one-time-per-launch weight conversion (tf32 + k-permute) ----
    {
        long n;
        n = (long)LL * QKV_O * HID;
        convperm_kernel<<<(unsigned)((n / 4 + 255) / 256), 256>>>(qkvw, wqkv_c, n);
        n = (long)LL * HID * QP;
        convperm_kernel<<<(unsigned)((n / 4 + 255) / 256), 256>>>(ow, wo_c, n);
        n = (long)LL * 2 * FF * HID;
        convperm_kernel<<<(unsigned)((n / 4 + 255) / 256), 256>>>(guw, wgu_c, n);
        n = (long)LL * HID * FF;
        convperm_kernel<<<(unsigned)((n / 4 + 255) / 256), 256>>>(dw, wdw_c, n);
    }

    detect_dtype_kernel<<<1, 1>>>((const unsigned int*)eq, flag);
    embed_kernel<<<SS, 256>>>(ids, eq, escale, ezero, flag, hbuf);

    for (int l = 0; l < LL; l++) {
        float* lkeys = keys  + (size_t)l * KVH * DD * SS;
        float* lvals = valsb + (size_t)l * KVH * SS * DD;

        // hn = rms(h, ln1)  (tf32-permuted)
        rmsnorm_kernel<true><<<SS, 256>>>(hbuf, ln1 + (size_t)l * HID, hn_u, HID);
        // qkv = hn @ qkv_w^T
        tgemmp_kernel<0><<<dim3(QKV_O / 128, SS / 128, 1), 128>>>(
            hn_u, HID, wqkv_c + (size_t)l * QKV_O * HID, HID,
            qkv, QKV_O, HID);
        // rope + split
        rope_split_kernel<<<(SS * QKV_O) / 256, 256>>>(qkv, cosE, sinE, qb, lkeys, lvals);
        // scores = q @ k (batched over heads)
        tgemm_kernel<0><<<dim3(SS / 128, SS / 128, HH), 256>>>(
            qb, DD, (long)SS * DD, lkeys, SS, (long)DD * SS, GG,
            scores, SS, (long)SS * SS, DD);
        softmax_kernel<<<dim3(SS, HH), 256>>>(scores, maskf);
        // ao = P @ v  -> tf32-permuted u32
        tgemm_kernel<2><<<dim3(DD / 128, SS / 128, HH), 256>>>(
            scores, SS, (long)SS * SS, lvals, DD, (long)SS * DD, GG,
            ao_u, HID, (long)DD, SS);
        // h += ao @ o_w^T
        tgemmp_kernel<1><<<dim3(HID / 128, SS / 128, 1), 128>>>(
            ao_u, QP, wo_c + (size_t)l * HID * QP, QP,
            hbuf, HID, QP);
        // hn = rms(h, ln2) (tf32-permuted)
        rmsnorm_kernel<true><<<SS, 256>>>(hbuf, ln2 + (size_t)l * HID, hn_u, HID);
        // gu = hn @ gate_up_w^T
        tgemmp_kernel<0><<<dim3(2 * FF / 128, SS / 128, 1), 128>>>(
            hn_u, HID, wgu_c + (size_t)l * 2 * FF * HID, HID,
            gu, 2 * FF, HID);
        // act = silu(gate)*up  -> tf32-permuted u32
        silu_kernel<<<(SS * FF) / 256, 256>>>(gu, act_u);
        // h += act @ down_w^T
        tgemmp_kernel<1><<<dim3(HID / 128, SS / 128, 1), 128>>>(
            act_u, FF, wdw_c + (size_t)l * HID * FF, FF,
            hbuf, HID, FF);
    }

    rmsnorm_kernel<false><<<1, 256>>>(hbuf + (size_t)(SS - 1) * HID, normw, hl, HID);
    lmhead_kernel<<<(VV * 32) / 256, 256>>>(hl, lmw, logits);
    argmax_kernel<<<1, 1024>>>(logits, (float*)d_out);
}

// round 11
// speedup vs baseline: 3.7651x; 1.0090x over previous
#include <cuda_runtime.h>
#include <cuda_bf16.h>
#include <cstdint>
#include <cmath>

// ---------------- problem constants ----------------
#define LL 2
#define HH 24
#define KVH 8
#define GG 3
#define DD 128
#define ROT 96
#define HALF 48
#define HID 3072
#define FF 8192
#define VV 32000
#define SS 1024
#define QP (HH*DD)          // 3072
#define KP (KVH*DD)         // 1024
#define QKV_O (QP + 2*KP)   // 5120
#define EPS 1e-6f
__device__ __constant__ float SCALE_C = 0.29730177875068026f;

// permuted column within 16-block: p = (c&~15) | ((c&3)<<2) | ((c>>2)&3)
#define PERMC(c) (((c) & ~15) | (((c) & 3) << 2) | (((c) >> 2) & 3))

// ---------------- scratch ----------------
#define OFF_H      0ull
#define OFF_HN     (OFF_H   + (size_t)SS*HID)
#define OFF_QKV    (OFF_HN  + (size_t)SS*HID)
#define OFF_Q      (OFF_QKV + (size_t)SS*QKV_O)
#define OFF_SC     (OFF_Q   + (size_t)HH*SS*DD)
#define OFF_PB     (OFF_SC  + (size_t)HH*SS*SS)
#define OFF_AO     (OFF_PB  + (size_t)HH*SS*SS)
#define OFF_GU     (OFF_AO  + (size_t)SS*HID)
#define OFF_ACT    (OFF_GU  + (size_t)SS*2*FF)
#define OFF_KT     (OFF_ACT + (size_t)SS*FF)
#define OFF_VT     (OFF_KT  + (size_t)KVH*SS*DD)
#define OFF_HL     (OFF_VT  + (size_t)KVH*DD*SS)
#define OFF_LG     (OFF_HL  + (size_t)HID)
#define OFF_FLAG   (OFF_LG  + (size_t)VV)
#define OFF_WQKV   (OFF_FLAG + 16)
#define OFF_WO     (OFF_WQKV + (size_t)LL*QKV_O*HID)
#define OFF_WGU    (OFF_WO   + (size_t)LL*HID*QP)
#define OFF_WDW    (OFF_WGU  + (size_t)LL*2*FF*HID)
#define SCRATCH_TOTAL (OFF_WDW + (size_t)LL*HID*FF)

__device__ float g_scratch[SCRATCH_TOTAL];

// output layout (4-byte elements)
#define OUT_KEYS   0ull
#define OUT_VALS   ((size_t)LL*KVH*DD*SS)
#define OUT_KVLEN  (2ull*LL*KVH*DD*SS)
#define OUT_TOKEN  (OUT_KVLEN + 1)

// ---------------- tf32 / cp.async helpers ----------------
__device__ __forceinline__ unsigned cvt_tf32(float x) {
    unsigned r;
    asm("cvt.rna.tf32.f32 %0, %1;" : "=r"(r) : "f"(x));
    return r;
}
__device__ __forceinline__ void mma_tf32(float* d, const unsigned* a, const unsigned* b) {
    asm("mma.sync.aligned.m16n8k8.row.col.f32.tf32.tf32.f32 "
        "{%0,%1,%2,%3}, {%4,%5,%6,%7}, {%8,%9}, {%0,%1,%2,%3};"
        : "+f"(d[0]), "+f"(d[1]), "+f"(d[2]), "+f"(d[3])
        : "r"(a[0]), "r"(a[1]), "r"(a[2]), "r"(a[3]),
          "r"(b[0]), "r"(b[1]));
}
__device__ __forceinline__ void cp_async16(void* dst, const void* src) {
    unsigned d = (unsigned)__cvta_generic_to_shared(dst);
    asm volatile("cp.async.cg.shared.global [%0], [%1], 16;\n" :: "r"(d), "l"(src));
}
__device__ __forceinline__ void cp_commit() { asm volatile("cp.async.commit_group;\n"); }
__device__ __forceinline__ void cp_wait1()  { asm volatile("cp.async.wait_group 1;\n"); }
__device__ __forceinline__ void cp_wait0()  { asm volatile("cp.async.wait_group 0;\n"); }

// ---------------- dtype probe for embed_q ----------------
__global__ void detect_dtype_kernel(const unsigned int* __restrict__ w,
                                    int* __restrict__ mode)
{
    bool all_small = true, all_f32 = true, all_bf16 = true;
    for (int i = 0; i < 64; i++) {
        unsigned int x = w[i];
        if (x > 255u) all_small = false;
        float f = __uint_as_float(x);
        if (!(f >= 0.f && f <= 255.f && f == rintf(f))) all_f32 = false;
        float f0 = __uint_as_float(x << 16);
        float f1 = __uint_as_float(x & 0xFFFF0000u);
        if (!(f0 >= 0.f && f0 <= 255.f && f0 == rintf(f0) &&
              f1 >= 0.f && f1 <= 255.f && f1 == rintf(f1))) all_bf16 = false;
    }
    *mode = all_small ? 1 : (all_f32 ? 2 : (all_bf16 ? 3 : 0));
}

// ---------------- embed ----------------
__global__ void embed_kernel(const int* __restrict__ ids,
                             const void* __restrict__ eq,
                             const float* __restrict__ escale,
                             const float* __restrict__ ezero,
                             const int* __restrict__ modep,
                             float* __restrict__ h)
{
    int s = blockIdx.x;
    int id = ids[s];
    float sc = escale[id], z = ezero[id];
    float* out = h + (size_t)s * HID;
    int mode = *modep;
    if (mode == 1) {
        const int* row = (const int*)eq + (size_t)id * HID;
        for (int j = threadIdx.x; j < HID; j += blockDim.x)
            out[j] = (float)row[j] * sc + z;
    } else if (mode == 2) {
        const float* row = (const float*)eq + (size_t)id * HID;
        for (int j = threadIdx.x; j < HID; j += blockDim.x)
            out[j] = row[j] * sc + z;
    } else if (mode == 3) {
        const unsigned short* row = (const unsigned short*)eq + (size_t)id * HID;
        for (int j = threadIdx.x; j < HID; j += blockDim.x)
            out[j] = __uint_as_float(((unsigned int)row[j]) << 16) * sc + z;
    } else {
        const unsigned char* row = (const unsigned char*)eq + (size_t)id * HID;
        for (int j = threadIdx.x; j < HID; j += blockDim.x)
            out[j] = (float)row[j] * sc + z;
    }
}

// ---------------- weight convert: fp32 -> tf32(u32), k-permuted ------------
__global__ void convperm_kernel(const float* __restrict__ src,
                                unsigned* __restrict__ dst, long n)
{
    long i4 = ((long)blockIdx.x * blockDim.x + threadIdx.x) * 4;
    if (i4 >= n) return;
    float4 v = *(const float4*)(src + i4);
    long base = i4 & ~15L;
    int j = (int)((i4 >> 2) & 3);
    dst[base + 0 + j] = cvt_tf32(v.x);
    dst[base + 4 + j] = cvt_tf32(v.y);
    dst[base + 8 + j] = cvt_tf32(v.z);
    dst[base + 12 + j] = cvt_tf32(v.w);
}

// ---------------- RMSNorm (optionally tf32-permuted output) ----------------
template<bool TF32P>
__global__ void rmsnorm_kernel(const float* __restrict__ in,
                               const float* __restrict__ w,
                               void* __restrict__ outv, int n)
{
    __shared__ float red[256];
    int row = blockIdx.x;
    const float* x = in + (size_t)row * n;
    float s = 0.f;
    for (int i = threadIdx.x; i < n; i += 256) { float v = x[i]; s += v * v; }
    red[threadIdx.x] = s; __syncthreads();
    for (int st = 128; st > 0; st >>= 1) {
        if (threadIdx.x < st) red[threadIdx.x] += red[threadIdx.x + st];
        __syncthreads();
    }
    float inv = rsqrtf(red[0] / (float)n + EPS);
    if (TF32P) {
        unsigned* y = (unsigned*)outv + (size_t)row * n;
        for (int i = threadIdx.x; i < n; i += 256)
            y[PERMC(i)] = cvt_tf32(w[i] * x[i] * inv);
    } else {
        float* y = (float*)outv + (size_t)row * n;
        for (int i = threadIdx.x; i < n; i += 256)
            y[i] = w[i] * x[i] * inv;
    }
}

// ---------------- pre-converted tf32 GEMM, batched, 3-stage ------------
// A [M,K] u32 tf32 k-permuted, B [N,K] u32 tf32 k-permuted (TRANSB form).
// CTA 128x128, 4 warps (128 thr), warp tile 64x64 (2x2 warp grid).
// Two-sweep MMA schedule: all a0*b0 MMAs, then all a1*b1 MMAs
// (per-accumulator order unchanged -> bit-identical numerics).
// OUTMODE: 0 = store f32, 1 = accumulate f32, 2 = store tf32-permuted u32.
template<int OUTMODE>
__global__ __launch_bounds__(128, 2) void tgemmp_kernel(
    const unsigned* __restrict__ A, int lda, long sA,
    const unsigned* __restrict__ B, int ldb, long sB, int gdivB,
    void* __restrict__ Cv, int ldc, long sC,
    int K)
{
    __shared__ __align__(16) unsigned smem[3 * 4096];   // per stage: A 2048 + B 2048

    int bz = blockIdx.z;
    A += (long)bz * sA;
    B += (long)(bz / gdivB) * sB;
    int m0 = blockIdx.y * 128, n0 = blockIdx.x * 128;
    int tid = threadIdx.x;
    int wid = tid >> 5, lane = tid & 31;
    int wm = (wid >> 1) * 64;          // 2 warps in m
    int wn = (wid & 1) * 64;           // 2 warps in n
    int g = lane >> 2, tig = lane & 3;

    float acc[4][8][4];
#pragma unroll
    for (int mi = 0; mi < 4; mi++)
#pragma unroll
        for (int ni = 0; ni < 8; ni++)
#pragma unroll
            for (int r = 0; r < 4; r++) acc[mi][ni][r] = 0.f;

    int nk = K >> 4;

#define PREFETCH_P(s, k0)                                                       \
    {                                                                           \
        unsigned* as = smem + (s) * 4096;                                       \
        unsigned* bs = as + 2048;                                               \
        _Pragma("unroll")                                                       \
        for (int i = 0; i < 4; i++) {                                           \
            int c = tid + i * 128;                                              \
            int r = c >> 2, cf = (c & 3) * 4;                                   \
            cp_async16(as + r * 16 + cf, A + (long)(m0 + r) * lda + (k0) + cf); \
            cp_async16(bs + r * 16 + cf, B + (long)(n0 + r) * ldb + (k0) + cf); \
        }                                                                       \
        cp_commit();                                                            \
    }

    PREFETCH_P(0, 0);
    if (nk > 1) PREFETCH_P(1, 16);

    int bufc = 0, bufp = 2;
    for (int it = 0; it < nk; it++) {
        if (it + 1 < nk) cp_wait1(); else cp_wait0();
        __syncthreads();
        if (it + 2 < nk) {
            PREFETCH_P(bufp, (it + 2) << 4);
            bufp = (bufp == 2) ? 0 : bufp + 1;
        }

        const unsigned* as = smem + bufc * 4096;
        const unsigned* bs = as + 2048;
        bufc = (bufc == 2) ? 0 : bufc + 1;

        uint4 qb[8], qa0[4], qa1[4];
#pragma unroll
        for (int ni = 0; ni < 8; ni++)
            qb[ni] = *(const uint4*)&bs[(wn + ni * 8 + g) * 16 + tig * 4];
#pragma unroll
        for (int mi = 0; mi < 4; mi++) {
            int mr = wm + mi * 16 + g;
            qa0[mi] = *(const uint4*)&as[mr * 16 + tig * 4];
            qa1[mi] = *(const uint4*)&as[(mr + 8) * 16 + tig * 4];
        }

        // sweep 0: kk = 0..7 contribution for every accumulator
#pragma unroll
        for (int mi = 0; mi < 4; mi++) {
            unsigned a0[4] = {qa0[mi].x, qa1[mi].x, qa0[mi].y, qa1[mi].y};
#pragma unroll
            for (int ni = 0; ni < 8; ni++) {
                unsigned b0[2] = {qb[ni].x, qb[ni].y};
                mma_tf32(acc[mi][ni], a0, b0);
            }
        }
        // sweep 1: kk = 8..15 contribution for every accumulator
#pragma unroll
        for (int mi = 0; mi < 4; mi++) {
            unsigned a1[4] = {qa0[mi].z, qa1[mi].z, qa0[mi].w, qa1[mi].w};
#pragma unroll
            for (int ni = 0; ni < 8; ni++) {
                unsigned b1[2] = {qb[ni].z, qb[ni].w};
                mma_tf32(acc[mi][ni], a1, b1);
            }
        }
    }

#pragma unroll
    for (int mi = 0; mi < 4; mi++) {
        int row = m0 + wm + mi * 16 + g;
#pragma unroll
        for (int ni = 0; ni < 8; ni++) {
            int col = n0 + wn + ni * 8 + 2 * tig;
            if (OUTMODE == 2) {
                unsigned* Cu = (unsigned*)Cv + (long)bz * sC;
                Cu[(long)row * ldc + PERMC(col)]     = cvt_tf32(acc[mi][ni][0]);
                Cu[(long)row * ldc + PERMC(col + 1)] = cvt_tf32(acc[mi][ni][1]);
                Cu[(long)(row + 8) * ldc + PERMC(col)]     = cvt_tf32(acc[mi][ni][2]);
                Cu[(long)(row + 8) * ldc + PERMC(col + 1)] = cvt_tf32(acc[mi][ni][3]);
            } else {
                float* C = (float*)Cv + (long)bz * sC;
                float2* p0 = (float2*)(C + (long)row * ldc + col);
                float2* p1 = (float2*)(C + (long)(row + 8) * ldc + col);
                if (OUTMODE == 1) {
                    float2 o0 = *p0, o1 = *p1;
                    o0.x += acc[mi][ni][0]; o0.y += acc[mi][ni][1];
                    o1.x += acc[mi][ni][2]; o1.y += acc[mi][ni][3];
                    *p0 = o0; *p1 = o1;
                } else {
                    *p0 = make_float2(acc[mi][ni][0], acc[mi][ni][1]);
                    *p1 = make_float2(acc[mi][ni][2], acc[mi][ni][3]);
                }
            }
        }
    }
}
#undef PREFETCH_P

// ---------------- split qkv + rope + scale ----------------
// Emits: f32 K/V caches (outputs), plus tf32-permuted u32 copies for the
// attention GEMMs: q_u [H][S][permD], kT_u [KV][S][permD], vT_u [KV][D][permS].
__global__ void rope_split_kernel(const float* __restrict__ qkv,
                                  const float* __restrict__ cosE,
                                  const float* __restrict__ sinE,
                                  unsigned* __restrict__ q_u,
                                  float* __restrict__ keys,     // [KV][D][S]
                                  float* __restrict__ vals,     // [KV][S][D]
                                  unsigned* __restrict__ kT_u,
                                  unsigned* __restrict__ vT_u)
{
    long idx = (long)blockIdx.x * blockDim.x + threadIdx.x;
    if (idx >= (long)SS * QKV_O) return;
    int s = (int)(idx / QKV_O);
    int c = (int)(idx % QKV_O);
    float v = qkv[idx];
    float scale = SCALE_C;
    if (c < QP) {
        int hh = c / DD, d = c % DD;
        float val = v * scale;
        if (d < ROT) {
            int pd = (d < HALF) ? d + HALF : d - HALF;
            float partner = qkv[(long)s * QKV_O + hh * DD + pd] * scale;
            float r = (d < HALF) ? -partner : partner;
            val = val * cosE[s * ROT + d] + r * sinE[s * ROT + d];
        }
        q_u[((size_t)hh * SS + s) * DD + PERMC(d)] = cvt_tf32(val);
    } else if (c < QP + KP) {
        int kc = c - QP;
        int kv = kc / DD, d = kc % DD;
        float val = v * scale;
        if (d < ROT) {
            int pd = (d < HALF) ? d + HALF : d - HALF;
            float partner = qkv[(long)s * QKV_O + QP + kv * DD + pd] * scale;
            float r = (d < HALF) ? -partner : partner;
            val = val * cosE[s * ROT + d] + r * sinE[s * ROT + d];
        }
        keys[((size_t)kv * DD + d) * SS + s] = val;
        kT_u[((size_t)kv * SS + s) * DD + PERMC(d)] = cvt_tf32(val);
    } else {
        int vc = c - QP - KP;
        int kv = vc / DD, d = vc % DD;
        vals[((size_t)kv * SS + s) * DD + d] = v;
        vT_u[((size_t)kv * DD + d) * SS + PERMC(s)] = cvt_tf32(v);
    }
}

// ---------------- softmax: read f32 scores, write tf32-permuted u32 probs ---
__global__ void softmax_kernel(const float* __restrict__ sc,
                               unsigned* __restrict__ pb,
                               const int* __restrict__ maskf)
{
    __shared__ float red[256];
    int s = blockIdx.x, h = blockIdx.y;
    const float* row = sc + ((size_t)h * SS + s) * SS;
    unsigned* prow = pb + ((size_t)h * SS + s) * SS;
    int mflag = maskf ? *maskf : 1;
    float mf = -128.f * (float)mflag;
    int tid = threadIdx.x;
    float vals[4];
    float lmax = -3.4e38f;
#pragma unroll
    for (int i = 0; i < 4; i++) {
        int t = tid + i * 256;
        float x = row[t] + ((t <= s) ? 0.f : mf);
        vals[i] = x;
        lmax = fmaxf(lmax, x);
    }
    red[tid] = lmax; __syncthreads();
    for (int st = 128; st > 0; st >>= 1) {
        if (tid < st) red[tid] = fmaxf(red[tid], red[tid + st]);
        __syncthreads();
    }
    float mx = red[0]; __syncthreads();
    float lsum = 0.f;
#pragma unroll
    for (int i = 0; i < 4; i++) { vals[i] = expf(vals[i] - mx); lsum += vals[i]; }
    red[tid] = lsum; __syncthreads();
    for (int st = 128; st > 0; st >>= 1) {
        if (tid < st) red[tid] += red[tid + st];
        __syncthreads();
    }
    float inv = 1.f / red[0];
#pragma unroll
    for (int i = 0; i < 4; i++) {
        int t = tid + i * 256;
        prow[PERMC(t)] = cvt_tf32(vals[i] * inv);
    }
}

// ---------------- SiLU(gate)*up -> tf32-permuted u32 ----------------
__global__ void silu_kernel(const float* __restrict__ gu, unsigned* __restrict__ act)
{
    long i = (long)blockIdx.x * blockDim.x + threadIdx.x;
    if (i >= (long)SS * FF) return;
    long s = i / FF, f = i % FF;
    float g = gu[s * 2 * FF + f];
    float u = gu[s * 2 * FF + FF + f];
    float v = (g / (1.f + expf(-g))) * u;
    act[(i & ~15L) | (long)(((int)(i & 3)) << 2) | (long)(((int)(i >> 2)) & 3)] = cvt_tf32(v);
}

// ---------------- lm_head ----------------
__global__ void lmhead_kernel(const float* __restrict__ hl,
                              const float* __restrict__ w,
                              float* __restrict__ logits)
{
    int gtid = blockIdx.x * blockDim.x + threadIdx.x;
    int warp = gtid >> 5, lane = gtid & 31;
    if (warp >= VV) return;
    const float* wr = w + (size_t)warp * HID;
    float s = 0.f;
    for (int k = lane; k < HID; k += 32) s = fmaf(hl[k], wr[k], s);
#pragma unroll
    for (int off = 16; off > 0; off >>= 1)
        s += __shfl_down_sync(0xffffffffu, s, off);
    if (lane == 0) logits[warp] = s;
}

// ---------------- argmax + scalar outputs ----------------
__global__ void argmax_kernel(const float* __restrict__ lg, float* __restrict__ outf)
{
    __shared__ float bv[1024];
    __shared__ int   bi[1024];
    int tid = threadIdx.x;
    float best = -3.4e38f; int bidx = 0;
    for (int t = tid; t < VV; t += 1024) {
        float v = lg[t];
        if (v > best) { best = v; bidx = t; }
    }
    bv[tid] = best; bi[tid] = bidx; __syncthreads();
    for (int st = 512; st > 0; st >>= 1) {
        if (tid < st) {
            if (bv[tid + st] > bv[tid] ||
                (bv[tid + st] == bv[tid] && bi[tid + st] < bi[tid])) {
                bv[tid] = bv[tid + st]; bi[tid] = bi[tid + st];
            }
        }
        __syncthreads();
    }
    if (tid == 0) {
        outf[OUT_KVLEN] = (float)SS;
        outf[OUT_TOKEN] = (float)bi[0];
    }
}

// ---------------- launch ----------------
extern "C" void kernel_launch(void* const* d_in, const int* in_sizes, int n_in,
                              void* d_out, int out_size)
{
    int i_ids = -1, i_mask = -1, i_eq = -1, i_lm = -1, i_esc = -1, i_ez = -1;
    int i_l1 = -1, i_l2 = -1, i_qkv = -1, i_ow = -1, i_gu = -1, i_dw = -1;
    int i_nw = -1, i_cos = -1, i_sin = -1;
    for (int i = 0; i < n_in; i++) {
        switch (in_sizes[i]) {
            case 1024:      i_ids = i; break;
            case 1:         i_mask = i; break;
            case 98304000:  if (i_eq < 0) i_eq = i; else i_lm = i; break;
            case 32000:     if (i_esc < 0) i_esc = i; else i_ez = i; break;
            case 6144:      if (i_l1 < 0) i_l1 = i; else i_l2 = i; break;
            case 31457280:  i_qkv = i; break;
            case 18874368:  i_ow = i; break;
            case 100663296: i_gu = i; break;
            case 50331648:  i_dw = i; break;
            case 3072:      i_nw = i; break;
            case 98304:     if (i_cos < 0) i_cos = i; else i_sin = i; break;
            default: break;
        }
    }
    const int*   ids    = (const int*)d_in[i_ids];
    const int*   maskf  = (i_mask >= 0) ? (const int*)d_in[i_mask] : nullptr;
    const void*  eq     = d_in[i_eq];
    const float* escale = (const float*)d_in[i_esc];
    const float* ezero  = (const float*)d_in[i_ez];
    const float* ln1    = (const float*)d_in[i_l1];
    const float* qkvw   = (const float*)d_in[i_qkv];
    const float* ow     = (const float*)d_in[i_ow];
    const float* ln2    = (const float*)d_in[i_l2];
    const float* guw    = (const float*)d_in[i_gu];
    const float* dw     = (const float*)d_in[i_dw];
    const float* normw  = (const float*)d_in[i_nw];
    const float* lmw    = (const float*)d_in[i_lm];
    const float* cosE   = (const float*)d_in[i_cos];
    const float* sinE   = (const float*)d_in[i_sin];
    float* out = (float*)d_out;

    float* scr = nullptr;
    cudaGetSymbolAddress((void**)&scr, g_scratch);
    float*    hbuf   = scr + OFF_H;
    unsigned* hn_u   = (unsigned*)(scr + OFF_HN);
    float*    qkv    = scr + OFF_QKV;
    unsigned* q_u    = (unsigned*)(scr + OFF_Q);
    float*    scores = scr + OFF_SC;
    unsigned* probs  = (unsigned*)(scr + OFF_PB);
    unsigned* ao_u   = (unsigned*)(scr + OFF_AO);
    float*    gu     = scr + OFF_GU;
    unsigned* act_u  = (unsigned*)(scr + OFF_ACT);
    unsigned* kT_u   = (unsigned*)(scr + OFF_KT);
    unsigned* vT_u   = (unsigned*)(scr + OFF_VT);
    float*    hl     = scr + OFF_HL;
    float*    logits = scr + OFF_LG;
    int*      flag   = (int*)(scr + OFF_FLAG);
    unsigned* wqkv_c = (unsigned*)(scr + OFF_WQKV);
    unsigned* wo_c   = (unsigned*)(scr + OFF_WO);
    unsigned* wgu_c  = (unsigned*)(scr + OFF_WGU);
    unsigned* wdw_c  = (unsigned*)(scr + OFF_WDW);
    float*    keys   = out + OUT_KEYS;
    float*    valsb  = out + OUT_VALS;

    // ---- one-time-per-launch weight conversion (tf32 + k-permute) ----
    {
        long n;
        n = (long)LL * QKV_O * HID;
        convperm_kernel<<<(unsigned)((n / 4 + 255) / 256), 256>>>(qkvw, wqkv_c, n);
        n = (long)LL * HID * QP;
        convperm_kernel<<<(unsigned)((n / 4 + 255) / 256), 256>>>(ow, wo_c, n);
        n = (long)LL * 2 * FF * HID;
        convperm_kernel<<<(unsigned)((n / 4 + 255) / 256), 256>>>(guw, wgu_c, n);
        n = (long)LL * HID * FF;
        convperm_kernel<<<(unsigned)((n / 4 + 255) / 256), 256>>>(dw, wdw_c, n);
    }

    detect_dtype_kernel<<<1, 1>>>((const unsigned int*)eq, flag);
    embed_kernel<<<SS, 256>>>(ids, eq, escale, ezero, flag, hbuf);

    for (int l = 0; l < LL; l++) {
        float* lkeys = keys  + (size_t)l * KVH * DD * SS;
        float* lvals = valsb + (size_t)l * KVH * SS * DD;

        // hn = rms(h, ln1)  (tf32-permuted)
        rmsnorm_kernel<true><<<SS, 256>>>(hbuf, ln1 + (size_t)l * HID, hn_u, HID);
        // qkv = hn @ qkv_w^T
        tgemmp_kernel<0><<<dim3(QKV_O / 128, SS / 128, 1), 128>>>(
            hn_u, HID, 0, wqkv_c + (size_t)l * QKV_O * HID, HID, 0, 1,
            qkv, QKV_O, 0, HID);
        // rope + split (f32 caches + tf32-permuted attention operands)
        rope_split_kernel<<<(SS * QKV_O) / 256, 256>>>(
            qkv, cosE, sinE, q_u, lkeys, lvals, kT_u, vT_u);
        // scores = q @ k^T (batched over heads)
        tgemmp_kernel<0><<<dim3(SS / 128, SS / 128, HH), 128>>>(
            q_u, DD, (long)SS * DD, kT_u, DD, (long)SS * DD, GG,
            scores, SS, (long)SS * SS, DD);
        // softmax -> tf32-permuted probs
        softmax_kernel<<<dim3(SS, HH), 256>>>(scores, probs, maskf);
        // ao = P @ v  -> tf32-permuted u32
        tgemmp_kernel<2><<<dim3(DD / 128, SS / 128, HH), 128>>>(
            probs, SS, (long)SS * SS, vT_u, SS, (long)DD * SS, GG,
            ao_u, HID, (long)DD, SS);
        // h += ao @ o_w^T
        tgemmp_kernel<1><<<dim3(HID / 128, SS / 128, 1), 128>>>(
            ao_u, QP, 0, wo_c + (size_t)l * HID * QP, QP, 0, 1,
            hbuf, HID, 0, QP);
        // hn = rms(h, ln2) (tf32-permuted)
        rmsnorm_kernel<true><<<SS, 256>>>(hbuf, ln2 + (size_t)l * HID, hn_u, HID);
        // gu = hn @ gate_up_w^T
        tgemmp_kernel<0><<<dim3(2 * FF / 128, SS / 128, 1), 128>>>(
            hn_u, HID, 0, wgu_c + (size_t)l * 2 * FF * HID, HID, 0, 1,
            gu, 2 * FF, 0, HID);
        // act = silu(gate)*up  -> tf32-permuted u32
        silu_kernel<<<(SS * FF) / 256, 256>>>(gu, act_u);
        // h += act @ down_w^T
        tgemmp_kernel<1><<<dim3(HID / 128, SS / 128, 1), 128>>>(
            act_u, FF, 0, wdw_c + (size_t)l * HID * FF, FF, 0, 1,
            hbuf, HID, 0, FF);
    }

    rmsnorm_kernel<false><<<1, 256>>>(hbuf + (size_t)(SS - 1) * HID, normw, hl, HID);
    lmhead_kernel<<<(VV * 32) / 256, 256>>>(hl, lmw, logits);
    argmax_kernel<<<1, 1024>>>(logits, (float*)d_out);
}